// round 1
// baseline (speedup 1.0000x reference)
#include <cuda_runtime.h>
#include <math.h>

// Problem constants
#define V_   32000
#define D_   1024
#define H_   16
#define HKV_ 4
#define FF_  4096
#define L_   8
#define HD_  64
#define NREP_ 4
#define B_   2
#define S_   1024
#define M_   (B_*S_)      // 2048 tokens
#define KVW_ (HKV_*HD_)   // 256
#define QW_  (H_*HD_)     // 1024

// ---------------- scratch (device globals; no allocation allowed) ----------
__device__ float g_x   [M_*D_];      // residual stream
__device__ float g_h   [M_*D_];      // normed activations
__device__ float g_q   [M_*QW_];
__device__ float g_k   [M_*KVW_];
__device__ float g_v   [M_*KVW_];
__device__ float g_att [M_*QW_];
__device__ float g_gate[M_*FF_];
__device__ float g_up  [M_*FF_];

// ---------------- embedding gather ----------------------------------------
__global__ void embed_kernel(const int* __restrict__ tokens,
                             const float* __restrict__ embed,
                             float* __restrict__ x) {
    int m = blockIdx.x;
    int t = tokens[m];
    const float4* src = (const float4*)(embed + (size_t)t * D_);
    float4*       dst = (float4*)(x + (size_t)m * D_);
    for (int i = threadIdx.x; i < D_ / 4; i += blockDim.x) dst[i] = src[i];
}

// ---------------- RMSNorm ---------------------------------------------------
__global__ void rmsnorm_kernel(const float* __restrict__ x,
                               const float* __restrict__ w,
                               float* __restrict__ out) {
    int m = blockIdx.x;
    const float* xr = x + (size_t)m * D_;
    float ss = 0.f;
    for (int i = threadIdx.x; i < D_; i += 256) { float v = xr[i]; ss += v * v; }
    ss += __shfl_xor_sync(0xffffffffu, ss, 16);
    ss += __shfl_xor_sync(0xffffffffu, ss, 8);
    ss += __shfl_xor_sync(0xffffffffu, ss, 4);
    ss += __shfl_xor_sync(0xffffffffu, ss, 2);
    ss += __shfl_xor_sync(0xffffffffu, ss, 1);
    __shared__ float red[8];
    int wid = threadIdx.x >> 5, lane = threadIdx.x & 31;
    if (lane == 0) red[wid] = ss;
    __syncthreads();
    float tot = red[0] + red[1] + red[2] + red[3] + red[4] + red[5] + red[6] + red[7];
    float rn = rsqrtf(tot / (float)D_ + 1e-6f);
    float* orow = out + (size_t)m * D_;
    for (int i = threadIdx.x; i < D_; i += 256) orow[i] = xr[i] * rn * w[i];
}

// ---------------- RoPE (in place, pairs (i, i+32) per thread) ---------------
__global__ void rope_kernel(float* __restrict__ x, int nheads, int total) {
    int idx = blockIdx.x * blockDim.x + threadIdx.x;
    if (idx >= total) return;
    int i    = idx & 31;
    int head = (idx >> 5) % nheads;
    int m    = idx / (32 * nheads);
    int s    = m % S_;
    // inv_freq = 10000^(-2i/64)
    float inv_freq = expf(-(float)(2 * i) * (1.0f / 64.0f) * 9.210340371976184f);
    float ang = (float)s * inv_freq;
    float sn, cs;
    sincosf(ang, &sn, &cs);
    float* base = x + (size_t)m * (nheads * HD_) + head * HD_;
    float x1 = base[i];
    float x2 = base[i + 32];
    base[i]      = x1 * cs - x2 * sn;
    base[i + 32] = x2 * cs + x1 * sn;
}

// ---------------- causal attention: one warp per query row -----------------
__global__ void attn_kernel(const float* __restrict__ q,
                            const float* __restrict__ k,
                            const float* __restrict__ v,
                            float* __restrict__ out) {
    int bh   = blockIdx.x;           // b*H + h
    int b    = bh / H_;
    int h    = bh % H_;
    int g    = h / NREP_;
    int warp = threadIdx.x >> 5;
    int lane = threadIdx.x & 31;
    int s    = blockIdx.y * 8 + warp;

    const float2* qp = (const float2*)(q + (size_t)(b * S_ + s) * QW_ + h * HD_);
    float2 qv = qp[lane];
    const float* kbase = k + (size_t)b * S_ * KVW_ + g * HD_;
    const float* vbase = v + (size_t)b * S_ * KVW_ + g * HD_;

    float mx = -INFINITY, l = 0.f, a0 = 0.f, a1 = 0.f;
    const float inv_scale = 0.125f;  // 1/sqrt(64)

    for (int j = 0; j <= s; j++) {
        float2 kv2 = *(const float2*)(kbase + (size_t)j * KVW_ + lane * 2);
        float p = qv.x * kv2.x + qv.y * kv2.y;
        p += __shfl_xor_sync(0xffffffffu, p, 16);
        p += __shfl_xor_sync(0xffffffffu, p, 8);
        p += __shfl_xor_sync(0xffffffffu, p, 4);
        p += __shfl_xor_sync(0xffffffffu, p, 2);
        p += __shfl_xor_sync(0xffffffffu, p, 1);
        float sc = p * inv_scale;
        float mn = fmaxf(mx, sc);
        float corr = __expf(mx - mn);
        float pe   = __expf(sc - mn);
        l = l * corr + pe;
        float2 vv = *(const float2*)(vbase + (size_t)j * KVW_ + lane * 2);
        a0 = a0 * corr + pe * vv.x;
        a1 = a1 * corr + pe * vv.y;
        mx = mn;
    }
    float invl = 1.f / l;
    float2* op = (float2*)(out + (size_t)(b * S_ + s) * QW_ + h * HD_);
    op[lane] = make_float2(a0 * invl, a1 * invl);
}

// ---------------- SiLU(gate) * up (in place into gate) ---------------------
__global__ void silumul_kernel(float* __restrict__ gate,
                               const float* __restrict__ up, int n) {
    int idx = blockIdx.x * blockDim.x + threadIdx.x;
    if (idx >= n) return;
    float gv = gate[idx];
    float sig = 1.f / (1.f + __expf(-gv));
    gate[idx] = gv * sig * up[idx];
}

// ---------------- SGEMM: C[M,N] = (ACC ? C : 0) + A[M,K] @ B ----------------
// TRANSB=false: B is [K,N] row-major.  TRANSB=true: B is [N,K] row-major (B^T).
// Tiles: 128x128x8, 256 threads, 8x8 per thread. Dims must divide tiles.
template <bool ACC, bool TRANSB>
__global__ __launch_bounds__(256, 2)
void gemm_kernel(const float* __restrict__ A, const float* __restrict__ B,
                 float* __restrict__ C, int M, int N, int K) {
    __shared__ float As[8][128];
    __shared__ float Bs[8][128];

    int tid  = threadIdx.x;
    int bcol = blockIdx.x * 128;
    int brow = blockIdx.y * 128;
    int tr   = tid / 16;         // 0..15
    int tc   = tid % 16;         // 0..15

    float acc[8][8];
#pragma unroll
    for (int i = 0; i < 8; i++)
#pragma unroll
        for (int j = 0; j < 8; j++) acc[i][j] = 0.f;

    int arow  = tid / 2,  acol4 = (tid % 2) * 4;   // A tile load
    int bk    = tid / 32, bn4   = (tid % 32) * 4;  // B NN tile load
    int tn    = tid / 2,  tk4   = (tid % 2) * 4;   // B NT tile load

    for (int k0 = 0; k0 < K; k0 += 8) {
        float4 av = *(const float4*)(A + (size_t)(brow + arow) * K + k0 + acol4);
        As[acol4 + 0][arow] = av.x;
        As[acol4 + 1][arow] = av.y;
        As[acol4 + 2][arow] = av.z;
        As[acol4 + 3][arow] = av.w;
        if (!TRANSB) {
            float4 bv = *(const float4*)(B + (size_t)(k0 + bk) * N + bcol + bn4);
            *(float4*)&Bs[bk][bn4] = bv;
        } else {
            float4 bv = *(const float4*)(B + (size_t)(bcol + tn) * K + k0 + tk4);
            Bs[tk4 + 0][tn] = bv.x;
            Bs[tk4 + 1][tn] = bv.y;
            Bs[tk4 + 2][tn] = bv.z;
            Bs[tk4 + 3][tn] = bv.w;
        }
        __syncthreads();
#pragma unroll
        for (int kk = 0; kk < 8; kk++) {
            float a[8], bfr[8];
#pragma unroll
            for (int i = 0; i < 8; i++) a[i] = As[kk][tr * 8 + i];
#pragma unroll
            for (int j = 0; j < 8; j++) bfr[j] = Bs[kk][tc * 8 + j];
#pragma unroll
            for (int i = 0; i < 8; i++)
#pragma unroll
                for (int j = 0; j < 8; j++) acc[i][j] += a[i] * bfr[j];
        }
        __syncthreads();
    }

#pragma unroll
    for (int i = 0; i < 8; i++) {
        float* crow = C + (size_t)(brow + tr * 8 + i) * N + bcol + tc * 8;
        if (ACC) {
            float4 c0 = *(float4*)(crow);
            float4 c1 = *(float4*)(crow + 4);
            c0.x += acc[i][0]; c0.y += acc[i][1]; c0.z += acc[i][2]; c0.w += acc[i][3];
            c1.x += acc[i][4]; c1.y += acc[i][5]; c1.z += acc[i][6]; c1.w += acc[i][7];
            *(float4*)(crow)     = c0;
            *(float4*)(crow + 4) = c1;
        } else {
            *(float4*)(crow)     = make_float4(acc[i][0], acc[i][1], acc[i][2], acc[i][3]);
            *(float4*)(crow + 4) = make_float4(acc[i][4], acc[i][5], acc[i][6], acc[i][7]);
        }
    }
}

// ---------------- driver ----------------------------------------------------
extern "C" void kernel_launch(void* const* d_in, const int* in_sizes, int n_in,
                              void* d_out, int out_size) {
    const int*   tokens     = (const int*)d_in[0];
    const float* embed      = (const float*)d_in[1];
    const float* wq         = (const float*)d_in[2];
    const float* wk         = (const float*)d_in[3];
    const float* wv         = (const float*)d_in[4];
    const float* wo         = (const float*)d_in[5];
    const float* w_gate     = (const float*)d_in[6];
    const float* w_up       = (const float*)d_in[7];
    const float* w_down     = (const float*)d_in[8];
    const float* norm1_w    = (const float*)d_in[9];
    const float* norm2_w    = (const float*)d_in[10];
    const float* final_norm = (const float*)d_in[11];
    float* out = (float*)d_out;

    float *x, *h, *q, *k, *v, *att, *gate, *up;
    cudaGetSymbolAddress((void**)&x,    g_x);
    cudaGetSymbolAddress((void**)&h,    g_h);
    cudaGetSymbolAddress((void**)&q,    g_q);
    cudaGetSymbolAddress((void**)&k,    g_k);
    cudaGetSymbolAddress((void**)&v,    g_v);
    cudaGetSymbolAddress((void**)&att,  g_att);
    cudaGetSymbolAddress((void**)&gate, g_gate);
    cudaGetSymbolAddress((void**)&up,   g_up);

    embed_kernel<<<M_, 256>>>(tokens, embed, x);

    for (int i = 0; i < L_; i++) {
        const float* wqi = wq + (size_t)i * D_ * QW_;
        const float* wki = wk + (size_t)i * D_ * KVW_;
        const float* wvi = wv + (size_t)i * D_ * KVW_;
        const float* woi = wo + (size_t)i * QW_ * D_;
        const float* wgi = w_gate + (size_t)i * D_ * FF_;
        const float* wui = w_up   + (size_t)i * D_ * FF_;
        const float* wdi = w_down + (size_t)i * FF_ * D_;

        rmsnorm_kernel<<<M_, 256>>>(x, norm1_w + (size_t)i * D_, h);

        gemm_kernel<false, false><<<dim3(QW_ / 128, M_ / 128), 256>>>(h, wqi, q, M_, QW_, D_);
        gemm_kernel<false, false><<<dim3(KVW_ / 128, M_ / 128), 256>>>(h, wki, k, M_, KVW_, D_);
        gemm_kernel<false, false><<<dim3(KVW_ / 128, M_ / 128), 256>>>(h, wvi, v, M_, KVW_, D_);

        rope_kernel<<<(M_ * H_ * 32 + 255) / 256, 256>>>(q, H_,   M_ * H_ * 32);
        rope_kernel<<<(M_ * HKV_ * 32 + 255) / 256, 256>>>(k, HKV_, M_ * HKV_ * 32);

        attn_kernel<<<dim3(B_ * H_, S_ / 8), 256>>>(q, k, v, att);

        // x += att @ wo
        gemm_kernel<true, false><<<dim3(D_ / 128, M_ / 128), 256>>>(att, woi, x, M_, D_, QW_);

        rmsnorm_kernel<<<M_, 256>>>(x, norm2_w + (size_t)i * D_, h);

        gemm_kernel<false, false><<<dim3(FF_ / 128, M_ / 128), 256>>>(h, wgi, gate, M_, FF_, D_);
        gemm_kernel<false, false><<<dim3(FF_ / 128, M_ / 128), 256>>>(h, wui, up,   M_, FF_, D_);

        silumul_kernel<<<(M_ * FF_ + 255) / 256, 256>>>(gate, up, M_ * FF_);

        // x += ff @ w_down
        gemm_kernel<true, false><<<dim3(D_ / 128, M_ / 128), 256>>>(gate, wdi, x, M_, D_, FF_);
    }

    rmsnorm_kernel<<<M_, 256>>>(x, final_norm, h);

    // logits = h @ embed^T  (embed is [V, D] row-major -> NT GEMM)
    gemm_kernel<false, true><<<dim3(V_ / 128, M_ / 128), 256>>>(h, embed, out, M_, V_, D_);
}

// round 5
// speedup vs baseline: 2.0031x; 2.0031x over previous
#include <cuda_runtime.h>
#include <cuda_bf16.h>
#include <math.h>
#include <stdint.h>

// Problem constants
#define V_   32000
#define D_   1024
#define H_   16
#define HKV_ 4
#define FF_  4096
#define L_   8
#define HD_  64
#define NREP_ 4
#define B_   2
#define S_   1024
#define M_   (B_*S_)      // 2048 tokens
#define KVW_ (HKV_*HD_)   // 256
#define QW_  (H_*HD_)     // 1024

// ---------------- scratch (device globals; no allocation allowed) ----------
__device__ float g_x   [M_*D_];
__device__ float g_h   [M_*D_];
__device__ float g_q   [M_*QW_];
__device__ float g_k   [M_*KVW_];
__device__ float g_v   [M_*KVW_];
__device__ float g_att [M_*QW_];
__device__ float g_gate[M_*FF_];
__device__ float g_up  [M_*FF_];
// transposed weights ([N,K] row-major) for NT GEMM
__device__ float g_wqt [D_*QW_];
__device__ float g_wkt [D_*KVW_];
__device__ float g_wvt [D_*KVW_];
__device__ float g_wot [QW_*D_];
__device__ float g_wgt [D_*FF_];
__device__ float g_wut [D_*FF_];
__device__ float g_wdt [FF_*D_];

// ---------------- bf16 helpers ---------------------------------------------
__device__ __forceinline__ uint16_t bfbits(__nv_bfloat16 h) {
    return *reinterpret_cast<uint16_t*>(&h);
}
// split float4 into hi (bf16) and lo (bf16 residual) packed pairs
__device__ __forceinline__ void split_store(uint16_t* hip, uint16_t* lop, float4 v) {
    __nv_bfloat16 h0 = __float2bfloat16_rn(v.x);
    __nv_bfloat16 h1 = __float2bfloat16_rn(v.y);
    __nv_bfloat16 h2 = __float2bfloat16_rn(v.z);
    __nv_bfloat16 h3 = __float2bfloat16_rn(v.w);
    float l0 = v.x - __bfloat162float(h0);
    float l1 = v.y - __bfloat162float(h1);
    float l2 = v.z - __bfloat162float(h2);
    float l3 = v.w - __bfloat162float(h3);
    uint32_t hA = (uint32_t)bfbits(h0) | ((uint32_t)bfbits(h1) << 16);
    uint32_t hB = (uint32_t)bfbits(h2) | ((uint32_t)bfbits(h3) << 16);
    __nv_bfloat16 e0 = __float2bfloat16_rn(l0);
    __nv_bfloat16 e1 = __float2bfloat16_rn(l1);
    __nv_bfloat16 e2 = __float2bfloat16_rn(l2);
    __nv_bfloat16 e3 = __float2bfloat16_rn(l3);
    uint32_t lA = (uint32_t)bfbits(e0) | ((uint32_t)bfbits(e1) << 16);
    uint32_t lB = (uint32_t)bfbits(e2) | ((uint32_t)bfbits(e3) << 16);
    *reinterpret_cast<uint2*>(hip) = make_uint2(hA, hB);
    *reinterpret_cast<uint2*>(lop) = make_uint2(lA, lB);
}

__device__ __forceinline__ void mma_bf16_16x8x16(float* c, uint32_t a0, uint32_t a1,
                                                 uint32_t a2, uint32_t a3,
                                                 uint32_t b0, uint32_t b1) {
    asm volatile(
        "mma.sync.aligned.m16n8k16.row.col.f32.bf16.bf16.f32 "
        "{%0,%1,%2,%3}, {%4,%5,%6,%7}, {%8,%9}, {%0,%1,%2,%3};"
        : "+f"(c[0]), "+f"(c[1]), "+f"(c[2]), "+f"(c[3])
        : "r"(a0), "r"(a1), "r"(a2), "r"(a3), "r"(b0), "r"(b1));
}

// ================= bf16x3 split GEMM (NT), fp32-equivalent =================
// C[M,N] = (ACC ? C : 0) + A[M,K] * B[N,K]^T, computed as
// Ahi*Bhi + Ahi*Blo + Alo*Bhi with fp32 accumulate.
// CTA tile 128x128, BK=32, 256 threads (8 warps, warp tile 64x32).
// SMEM row pitch 40 u16 (64B data + 16B pad) -> conflict-free fragments.
#define P16_ 40
#define TILE_U16 (128 * P16_)                  // 5120 u16 = 10240 B
#define BUF_U16  (4 * TILE_U16)                // Ahi,Alo,Bhi,Blo
#define GEMM_SMEM_BYTES (2 * BUF_U16 * 2)      // double buffered = 81920 B

template <bool ACC>
__global__ __launch_bounds__(256)
void bf16x3_gemm(const float* __restrict__ A, const float* __restrict__ B,
                 float* __restrict__ C, int M, int N, int K) {
    extern __shared__ char smem_raw[];
    uint16_t* smem = reinterpret_cast<uint16_t*>(smem_raw);

    const int tid    = threadIdx.x;
    const int wid    = tid >> 5;
    const int lane   = tid & 31;
    const int g      = lane >> 2;     // 0..7
    const int t      = lane & 3;      // 0..3
    const int warp_m = (wid & 1) * 64;
    const int warp_n = (wid >> 1) * 32;
    const int brow   = blockIdx.y * 128;
    const int bcol   = blockIdx.x * 128;

    float acc[4][4][4];
#pragma unroll
    for (int i = 0; i < 4; i++)
#pragma unroll
        for (int j = 0; j < 4; j++)
#pragma unroll
            for (int r = 0; r < 4; r++) acc[i][j][r] = 0.f;

    const int lrow = tid >> 3;        // 0..31
    const int lc4  = (tid & 7) * 4;   // 0,4,..28

    const int niter = K >> 5;

    // prologue: tile 0 -> buffer 0
    {
        uint16_t* Ahi = smem;
        uint16_t* Alo = Ahi + TILE_U16;
        uint16_t* Bhi = Alo + TILE_U16;
        uint16_t* Blo = Bhi + TILE_U16;
#pragma unroll
        for (int j = 0; j < 4; j++) {
            int row = j * 32 + lrow;
            float4 av = *(const float4*)(A + (size_t)(brow + row) * K + lc4);
            split_store(Ahi + row * P16_ + lc4, Alo + row * P16_ + lc4, av);
            float4 bv = *(const float4*)(B + (size_t)(bcol + row) * K + lc4);
            split_store(Bhi + row * P16_ + lc4, Blo + row * P16_ + lc4, bv);
        }
    }
    __syncthreads();

    for (int it = 0; it < niter; it++) {
        const int buf = it & 1;
        uint16_t* Ahi = smem + buf * BUF_U16;
        uint16_t* Alo = Ahi + TILE_U16;
        uint16_t* Bhi = Alo + TILE_U16;
        uint16_t* Blo = Bhi + TILE_U16;

        // prefetch next K tile into registers
        float4 anext[4], bnext[4];
        if (it + 1 < niter) {
            const int k0 = (it + 1) << 5;
#pragma unroll
            for (int j = 0; j < 4; j++) {
                int row = j * 32 + lrow;
                anext[j] = *(const float4*)(A + (size_t)(brow + row) * K + k0 + lc4);
                bnext[j] = *(const float4*)(B + (size_t)(bcol + row) * K + k0 + lc4);
            }
        }

        // 2 k16 steps per 32-K tile
#pragma unroll
        for (int ks = 0; ks < 2; ks++) {
            const int kb = ks * 16;
            uint32_t ah[4][4], al[4][4];
#pragma unroll
            for (int mt = 0; mt < 4; mt++) {
                int ro = (warp_m + mt * 16 + g) * P16_ + kb + 2 * t;
                const uint16_t* ph = Ahi + ro;
                const uint16_t* pl = Alo + ro;
                ah[mt][0] = *(const uint32_t*)(ph);
                ah[mt][1] = *(const uint32_t*)(ph + 8 * P16_);
                ah[mt][2] = *(const uint32_t*)(ph + 8);
                ah[mt][3] = *(const uint32_t*)(ph + 8 * P16_ + 8);
                al[mt][0] = *(const uint32_t*)(pl);
                al[mt][1] = *(const uint32_t*)(pl + 8 * P16_);
                al[mt][2] = *(const uint32_t*)(pl + 8);
                al[mt][3] = *(const uint32_t*)(pl + 8 * P16_ + 8);
            }
            uint32_t bh[4][2], bl[4][2];
#pragma unroll
            for (int nt = 0; nt < 4; nt++) {
                int ro = (warp_n + nt * 8 + g) * P16_ + kb + 2 * t;
                const uint16_t* ph = Bhi + ro;
                const uint16_t* pl = Blo + ro;
                bh[nt][0] = *(const uint32_t*)(ph);
                bh[nt][1] = *(const uint32_t*)(ph + 8);
                bl[nt][0] = *(const uint32_t*)(pl);
                bl[nt][1] = *(const uint32_t*)(pl + 8);
            }
#pragma unroll
            for (int mt = 0; mt < 4; mt++)
#pragma unroll
                for (int nt = 0; nt < 4; nt++) {
                    mma_bf16_16x8x16(acc[mt][nt], ah[mt][0], ah[mt][1], ah[mt][2], ah[mt][3],
                                     bh[nt][0], bh[nt][1]);
                    mma_bf16_16x8x16(acc[mt][nt], ah[mt][0], ah[mt][1], ah[mt][2], ah[mt][3],
                                     bl[nt][0], bl[nt][1]);
                    mma_bf16_16x8x16(acc[mt][nt], al[mt][0], al[mt][1], al[mt][2], al[mt][3],
                                     bh[nt][0], bh[nt][1]);
                }
        }

        __syncthreads();
        if (it + 1 < niter) {
            uint16_t* Ahn = smem + ((it + 1) & 1) * BUF_U16;
            uint16_t* Aln = Ahn + TILE_U16;
            uint16_t* Bhn = Aln + TILE_U16;
            uint16_t* Bln = Bhn + TILE_U16;
#pragma unroll
            for (int j = 0; j < 4; j++) {
                int row = j * 32 + lrow;
                split_store(Ahn + row * P16_ + lc4, Aln + row * P16_ + lc4, anext[j]);
                split_store(Bhn + row * P16_ + lc4, Bln + row * P16_ + lc4, bnext[j]);
            }
            __syncthreads();
        }
    }

    // epilogue (m16n8 C layout: c0,c1 at row g, cols 2t,2t+1; c2,c3 at row g+8)
#pragma unroll
    for (int mt = 0; mt < 4; mt++) {
        int r0 = brow + warp_m + mt * 16 + g;
#pragma unroll
        for (int nt = 0; nt < 4; nt++) {
            int c0 = bcol + warp_n + nt * 8 + t * 2;
            float2* p0 = (float2*)(C + (size_t)r0 * N + c0);
            float2* p1 = (float2*)(C + (size_t)(r0 + 8) * N + c0);
            float2 v0 = make_float2(acc[mt][nt][0], acc[mt][nt][1]);
            float2 v1 = make_float2(acc[mt][nt][2], acc[mt][nt][3]);
            if (ACC) {
                float2 o0 = *p0, o1 = *p1;
                v0.x += o0.x; v0.y += o0.y;
                v1.x += o1.x; v1.y += o1.y;
            }
            *p0 = v0;
            *p1 = v1;
        }
    }
}

// ---------------- weight transpose [K,N] -> [N,K] ---------------------------
__global__ void transpose_kernel(const float* __restrict__ in,
                                 float* __restrict__ out, int K, int N) {
    __shared__ float tile[32][33];
    int kx = blockIdx.x * 32, ny = blockIdx.y * 32;
    int tx = threadIdx.x, ty = threadIdx.y;
#pragma unroll
    for (int r = ty; r < 32; r += 8)
        tile[r][tx] = in[(size_t)(kx + r) * N + ny + tx];
    __syncthreads();
#pragma unroll
    for (int r = ty; r < 32; r += 8)
        out[(size_t)(ny + r) * K + kx + tx] = tile[tx][r];
}

// ---------------- embedding gather ----------------------------------------
__global__ void embed_kernel(const int* __restrict__ tokens,
                             const float* __restrict__ embed,
                             float* __restrict__ x) {
    int m = blockIdx.x;
    int tkn = tokens[m];
    const float4* src = (const float4*)(embed + (size_t)tkn * D_);
    float4*       dst = (float4*)(x + (size_t)m * D_);
    for (int i = threadIdx.x; i < D_ / 4; i += blockDim.x) dst[i] = src[i];
}

// ---------------- RMSNorm ---------------------------------------------------
__global__ void rmsnorm_kernel(const float* __restrict__ x,
                               const float* __restrict__ w,
                               float* __restrict__ out) {
    int m = blockIdx.x;
    const float* xr = x + (size_t)m * D_;
    float ss = 0.f;
    for (int i = threadIdx.x; i < D_; i += 256) { float v = xr[i]; ss += v * v; }
    ss += __shfl_xor_sync(0xffffffffu, ss, 16);
    ss += __shfl_xor_sync(0xffffffffu, ss, 8);
    ss += __shfl_xor_sync(0xffffffffu, ss, 4);
    ss += __shfl_xor_sync(0xffffffffu, ss, 2);
    ss += __shfl_xor_sync(0xffffffffu, ss, 1);
    __shared__ float red[8];
    int wid = threadIdx.x >> 5, lane = threadIdx.x & 31;
    if (lane == 0) red[wid] = ss;
    __syncthreads();
    float tot = red[0] + red[1] + red[2] + red[3] + red[4] + red[5] + red[6] + red[7];
    float rn = rsqrtf(tot / (float)D_ + 1e-6f);
    float* orow = out + (size_t)m * D_;
    for (int i = threadIdx.x; i < D_; i += 256) orow[i] = xr[i] * rn * w[i];
}

// ---------------- RoPE (in place, pairs (i, i+32) per thread) ---------------
__global__ void rope_kernel(float* __restrict__ x, int nheads, int total) {
    int idx = blockIdx.x * blockDim.x + threadIdx.x;
    if (idx >= total) return;
    int i    = idx & 31;
    int head = (idx >> 5) % nheads;
    int m    = idx / (32 * nheads);
    int s    = m % S_;
    float inv_freq = expf(-(float)(2 * i) * (1.0f / 64.0f) * 9.210340371976184f);
    float ang = (float)s * inv_freq;
    float sn, cs;
    sincosf(ang, &sn, &cs);
    float* base = x + (size_t)m * (nheads * HD_) + head * HD_;
    float x1 = base[i];
    float x2 = base[i + 32];
    base[i]      = x1 * cs - x2 * sn;
    base[i + 32] = x2 * cs + x1 * sn;
}

// ---------------- causal attention: one warp per query row -----------------
__global__ void attn_kernel(const float* __restrict__ q,
                            const float* __restrict__ k,
                            const float* __restrict__ v,
                            float* __restrict__ out) {
    int bh   = blockIdx.x;
    int b    = bh / H_;
    int h    = bh % H_;
    int g    = h / NREP_;
    int warp = threadIdx.x >> 5;
    int lane = threadIdx.x & 31;
    int s    = blockIdx.y * 8 + warp;

    const float2* qp = (const float2*)(q + (size_t)(b * S_ + s) * QW_ + h * HD_);
    float2 qv = qp[lane];
    const float* kbase = k + (size_t)b * S_ * KVW_ + g * HD_;
    const float* vbase = v + (size_t)b * S_ * KVW_ + g * HD_;

    float mx = -INFINITY, l = 0.f, a0 = 0.f, a1 = 0.f;
    const float inv_scale = 0.125f;

    for (int j = 0; j <= s; j++) {
        float2 kv2 = *(const float2*)(kbase + (size_t)j * KVW_ + lane * 2);
        float p = qv.x * kv2.x + qv.y * kv2.y;
        p += __shfl_xor_sync(0xffffffffu, p, 16);
        p += __shfl_xor_sync(0xffffffffu, p, 8);
        p += __shfl_xor_sync(0xffffffffu, p, 4);
        p += __shfl_xor_sync(0xffffffffu, p, 2);
        p += __shfl_xor_sync(0xffffffffu, p, 1);
        float sc = p * inv_scale;
        float mn = fmaxf(mx, sc);
        float corr = __expf(mx - mn);
        float pe   = __expf(sc - mn);
        l = l * corr + pe;
        float2 vv = *(const float2*)(vbase + (size_t)j * KVW_ + lane * 2);
        a0 = a0 * corr + pe * vv.x;
        a1 = a1 * corr + pe * vv.y;
        mx = mn;
    }
    float invl = 1.f / l;
    float2* op = (float2*)(out + (size_t)(b * S_ + s) * QW_ + h * HD_);
    op[lane] = make_float2(a0 * invl, a1 * invl);
}

// ---------------- SiLU(gate) * up (in place into gate) ---------------------
__global__ void silumul_kernel(float* __restrict__ gate,
                               const float* __restrict__ up, int n) {
    int idx = blockIdx.x * blockDim.x + threadIdx.x;
    if (idx >= n) return;
    float gv = gate[idx];
    float sig = 1.f / (1.f + __expf(-gv));
    gate[idx] = gv * sig * up[idx];
}

// ---------------- driver ----------------------------------------------------
extern "C" void kernel_launch(void* const* d_in, const int* in_sizes, int n_in,
                              void* d_out, int out_size) {
    const int*   tokens     = (const int*)d_in[0];
    const float* embed      = (const float*)d_in[1];
    const float* wq         = (const float*)d_in[2];
    const float* wk         = (const float*)d_in[3];
    const float* wv         = (const float*)d_in[4];
    const float* wo         = (const float*)d_in[5];
    const float* w_gate     = (const float*)d_in[6];
    const float* w_up       = (const float*)d_in[7];
    const float* w_down     = (const float*)d_in[8];
    const float* norm1_w    = (const float*)d_in[9];
    const float* norm2_w    = (const float*)d_in[10];
    const float* final_norm = (const float*)d_in[11];
    float* out = (float*)d_out;

    float *x, *h, *q, *k, *v, *att, *gate, *up;
    float *wqt, *wkt, *wvt, *wot, *wgt, *wut, *wdt;
    cudaGetSymbolAddress((void**)&x,    g_x);
    cudaGetSymbolAddress((void**)&h,    g_h);
    cudaGetSymbolAddress((void**)&q,    g_q);
    cudaGetSymbolAddress((void**)&k,    g_k);
    cudaGetSymbolAddress((void**)&v,    g_v);
    cudaGetSymbolAddress((void**)&att,  g_att);
    cudaGetSymbolAddress((void**)&gate, g_gate);
    cudaGetSymbolAddress((void**)&up,   g_up);
    cudaGetSymbolAddress((void**)&wqt,  g_wqt);
    cudaGetSymbolAddress((void**)&wkt,  g_wkt);
    cudaGetSymbolAddress((void**)&wvt,  g_wvt);
    cudaGetSymbolAddress((void**)&wot,  g_wot);
    cudaGetSymbolAddress((void**)&wgt,  g_wgt);
    cudaGetSymbolAddress((void**)&wut,  g_wut);
    cudaGetSymbolAddress((void**)&wdt,  g_wdt);

    cudaFuncSetAttribute(bf16x3_gemm<false>,
                         cudaFuncAttributeMaxDynamicSharedMemorySize, GEMM_SMEM_BYTES);
    cudaFuncSetAttribute(bf16x3_gemm<true>,
                         cudaFuncAttributeMaxDynamicSharedMemorySize, GEMM_SMEM_BYTES);

    embed_kernel<<<M_, 256>>>(tokens, embed, x);

    dim3 t32(32, 8);
    for (int i = 0; i < L_; i++) {
        const float* wqi = wq + (size_t)i * D_ * QW_;
        const float* wki = wk + (size_t)i * D_ * KVW_;
        const float* wvi = wv + (size_t)i * D_ * KVW_;
        const float* woi = wo + (size_t)i * QW_ * D_;
        const float* wgi = w_gate + (size_t)i * D_ * FF_;
        const float* wui = w_up   + (size_t)i * D_ * FF_;
        const float* wdi = w_down + (size_t)i * FF_ * D_;

        transpose_kernel<<<dim3(D_ / 32, QW_ / 32),  t32>>>(wqi, wqt, D_, QW_);
        transpose_kernel<<<dim3(D_ / 32, KVW_ / 32), t32>>>(wki, wkt, D_, KVW_);
        transpose_kernel<<<dim3(D_ / 32, KVW_ / 32), t32>>>(wvi, wvt, D_, KVW_);
        transpose_kernel<<<dim3(QW_ / 32, D_ / 32),  t32>>>(woi, wot, QW_, D_);
        transpose_kernel<<<dim3(D_ / 32, FF_ / 32),  t32>>>(wgi, wgt, D_, FF_);
        transpose_kernel<<<dim3(D_ / 32, FF_ / 32),  t32>>>(wui, wut, D_, FF_);
        transpose_kernel<<<dim3(FF_ / 32, D_ / 32),  t32>>>(wdi, wdt, FF_, D_);

        rmsnorm_kernel<<<M_, 256>>>(x, norm1_w + (size_t)i * D_, h);

        bf16x3_gemm<false><<<dim3(QW_ / 128, M_ / 128), 256, GEMM_SMEM_BYTES>>>(h, wqt, q, M_, QW_, D_);
        bf16x3_gemm<false><<<dim3(KVW_ / 128, M_ / 128), 256, GEMM_SMEM_BYTES>>>(h, wkt, k, M_, KVW_, D_);
        bf16x3_gemm<false><<<dim3(KVW_ / 128, M_ / 128), 256, GEMM_SMEM_BYTES>>>(h, wvt, v, M_, KVW_, D_);

        rope_kernel<<<(M_ * H_ * 32 + 255) / 256, 256>>>(q, H_,   M_ * H_ * 32);
        rope_kernel<<<(M_ * HKV_ * 32 + 255) / 256, 256>>>(k, HKV_, M_ * HKV_ * 32);

        attn_kernel<<<dim3(B_ * H_, S_ / 8), 256>>>(q, k, v, att);

        bf16x3_gemm<true><<<dim3(D_ / 128, M_ / 128), 256, GEMM_SMEM_BYTES>>>(att, wot, x, M_, D_, QW_);

        rmsnorm_kernel<<<M_, 256>>>(x, norm2_w + (size_t)i * D_, h);

        bf16x3_gemm<false><<<dim3(FF_ / 128, M_ / 128), 256, GEMM_SMEM_BYTES>>>(h, wgt, gate, M_, FF_, D_);
        bf16x3_gemm<false><<<dim3(FF_ / 128, M_ / 128), 256, GEMM_SMEM_BYTES>>>(h, wut, up,   M_, FF_, D_);

        silumul_kernel<<<(M_ * FF_ + 255) / 256, 256>>>(gate, up, M_ * FF_);

        bf16x3_gemm<true><<<dim3(D_ / 128, M_ / 128), 256, GEMM_SMEM_BYTES>>>(gate, wdt, x, M_, D_, FF_);
    }

    rmsnorm_kernel<<<M_, 256>>>(x, final_norm, h);

    // logits = h @ embed^T ; embed is [V, D] = [N, K] row-major already
    bf16x3_gemm<false><<<dim3(V_ / 128, M_ / 128), 256, GEMM_SMEM_BYTES>>>(h, embed, out, M_, V_, D_);
}

// round 6
// speedup vs baseline: 2.2490x; 1.1227x over previous
#include <cuda_runtime.h>
#include <cuda_bf16.h>
#include <math.h>
#include <stdint.h>

// Problem constants
#define V_   32000
#define D_   1024
#define H_   16
#define HKV_ 4
#define FF_  4096
#define L_   8
#define HD_  64
#define NREP_ 4
#define B_   2
#define S_   1024
#define M_   (B_*S_)      // 2048 tokens
#define KVW_ (HKV_*HD_)   // 256
#define QW_  (H_*HD_)     // 1024

// ---------------- scratch (device globals; no allocation allowed) ----------
__device__ float g_x   [M_*D_];
__device__ float g_q   [M_*QW_];
__device__ float g_k   [M_*KVW_];
__device__ float g_v   [M_*KVW_];
__device__ float g_gate[M_*FF_];
__device__ float g_up  [M_*FF_];
// split (hi/lo bf16) activations
__device__ __align__(16) uint16_t g_h_hi  [M_*D_],  g_h_lo  [M_*D_];
__device__ __align__(16) uint16_t g_att_hi[M_*QW_], g_att_lo[M_*QW_];
__device__ __align__(16) uint16_t g_gs_hi [M_*FF_], g_gs_lo [M_*FF_];
// split transposed weights ([N,K] row-major), reused per layer
__device__ __align__(16) uint16_t g_wqt_hi[QW_*D_],  g_wqt_lo[QW_*D_];
__device__ __align__(16) uint16_t g_wkt_hi[KVW_*D_], g_wkt_lo[KVW_*D_];
__device__ __align__(16) uint16_t g_wvt_hi[KVW_*D_], g_wvt_lo[KVW_*D_];
__device__ __align__(16) uint16_t g_wot_hi[D_*QW_],  g_wot_lo[D_*QW_];
__device__ __align__(16) uint16_t g_wgt_hi[FF_*D_],  g_wgt_lo[FF_*D_];
__device__ __align__(16) uint16_t g_wut_hi[FF_*D_],  g_wut_lo[FF_*D_];
__device__ __align__(16) uint16_t g_wdt_hi[D_*FF_],  g_wdt_lo[D_*FF_];
// split embed table (for logits GEMM B operand)
__device__ __align__(16) uint16_t g_emb_hi[V_*D_],   g_emb_lo[V_*D_];

// ---------------- helpers ---------------------------------------------------
__device__ __forceinline__ uint32_t smem_u32(const void* p) {
    uint32_t a;
    asm("{ .reg .u64 t; cvta.to.shared.u64 t, %1; cvt.u32.u64 %0, t; }"
        : "=r"(a) : "l"(p));
    return a;
}
__device__ __forceinline__ uint16_t bfbits(__nv_bfloat16 h) {
    return *reinterpret_cast<uint16_t*>(&h);
}
__device__ __forceinline__ void split_w(uint16_t* hi, uint16_t* lo, size_t idx, float v) {
    __nv_bfloat16 hb = __float2bfloat16_rn(v);
    float l = v - __bfloat162float(hb);
    __nv_bfloat16 lb = __float2bfloat16_rn(l);
    hi[idx] = bfbits(hb);
    lo[idx] = bfbits(lb);
}

#define CP_A16(s, g) asm volatile("cp.async.cg.shared.global [%0], [%1], 16;" :: "r"(s), "l"(g))
#define CP_COMMIT()  asm volatile("cp.async.commit_group;" ::: "memory")
#define CP_WAIT1()   asm volatile("cp.async.wait_group 1;" ::: "memory")
#define CP_WAIT0()   asm volatile("cp.async.wait_group 0;" ::: "memory")

__device__ __forceinline__ void ldm_x4(uint32_t a, uint32_t& r0, uint32_t& r1,
                                       uint32_t& r2, uint32_t& r3) {
    asm volatile("ldmatrix.sync.aligned.m8n8.x4.shared.b16 {%0,%1,%2,%3}, [%4];"
                 : "=r"(r0), "=r"(r1), "=r"(r2), "=r"(r3) : "r"(a));
}

__device__ __forceinline__ void mma_bf16_16x8x16(float* c, uint32_t a0, uint32_t a1,
                                                 uint32_t a2, uint32_t a3,
                                                 uint32_t b0, uint32_t b1) {
    asm volatile(
        "mma.sync.aligned.m16n8k16.row.col.f32.bf16.bf16.f32 "
        "{%0,%1,%2,%3}, {%4,%5,%6,%7}, {%8,%9}, {%0,%1,%2,%3};"
        : "+f"(c[0]), "+f"(c[1]), "+f"(c[2]), "+f"(c[3])
        : "r"(a0), "r"(a1), "r"(a2), "r"(a3), "r"(b0), "r"(b1));
}

// ================= bf16x3 split GEMM (NT), pre-split operands ==============
// C[M,N] = (ACC ? C : 0) + (Ahi+Alo)[M,K] * (Bhi+Blo)[N,K]^T  (drop lo*lo).
// CTA tile 128x128, BK=32, 256 threads (8 warps, warp tile 64x32).
// SMEM: 4 components x 128 rows x 80B pitch (64B data + 16B pad), dbl buffer.
#define PITCHB 80
#define COMPB  (128 * PITCHB)     // 10240 B
#define BUFB   (4 * COMPB)        // 40960 B
#define GEMM_SMEM_BYTES (2 * BUFB)

__device__ __forceinline__ void issue_tile(uint32_t sbuf,
    const uint16_t* Ahi, const uint16_t* Alo,
    const uint16_t* Bhi, const uint16_t* Blo,
    int brow, int bcol, int K, int k0, int tid)
{
#pragma unroll
    for (int c = 0; c < 2; c++) {
        int idx = tid + c * 256;
        int row = idx >> 2;
        int co  = (idx & 3) * 8;       // element offset within 32-wide K tile
        uint32_t so = (uint32_t)(row * PITCHB + co * 2);
        size_t goA = (size_t)(brow + row) * K + k0 + co;
        size_t goB = (size_t)(bcol + row) * K + k0 + co;
        CP_A16(sbuf + so,             Ahi + goA);
        CP_A16(sbuf + COMPB + so,     Alo + goA);
        CP_A16(sbuf + 2 * COMPB + so, Bhi + goB);
        CP_A16(sbuf + 3 * COMPB + so, Blo + goB);
    }
}

template <bool ACC>
__global__ __launch_bounds__(256)
void bf16x3_gemm(const uint16_t* __restrict__ Ahi, const uint16_t* __restrict__ Alo,
                 const uint16_t* __restrict__ Bhi, const uint16_t* __restrict__ Blo,
                 float* __restrict__ C, int M, int N, int K) {
    extern __shared__ char smem[];
    const uint32_t sb = smem_u32(smem);
    const int tid    = threadIdx.x;
    const int wid    = tid >> 5;
    const int lane   = tid & 31;
    const int warp_m = (wid & 1) * 64;
    const int warp_n = (wid >> 1) * 32;
    const int brow   = blockIdx.y * 128;
    const int bcol   = blockIdx.x * 128;

    float acc[4][4][4];
#pragma unroll
    for (int i = 0; i < 4; i++)
#pragma unroll
        for (int j = 0; j < 4; j++)
#pragma unroll
            for (int r = 0; r < 4; r++) acc[i][j][r] = 0.f;

    const int niter = K >> 5;

    issue_tile(sb, Ahi, Alo, Bhi, Blo, brow, bcol, K, 0, tid);
    CP_COMMIT();

    // ldmatrix lane address components
    const int a_r = lane & 15;                      // row within 16
    const int a_h = (lane >> 4) & 1;                // k half (8 elems = 16B)
    const int b_r = ((lane >> 4) & 1) * 8 + (lane & 7);
    const int b_h = (lane >> 3) & 1;

    for (int it = 0; it < niter; it++) {
        const uint32_t buf = sb + (uint32_t)(it & 1) * BUFB;
        if (it + 1 < niter) {
            issue_tile(sb + (uint32_t)((it + 1) & 1) * BUFB, Ahi, Alo, Bhi, Blo,
                       brow, bcol, K, (it + 1) << 5, tid);
            CP_COMMIT();
            CP_WAIT1();
        } else {
            CP_WAIT0();
        }
        __syncthreads();

        const uint32_t Ah = buf, Al = buf + COMPB, Bh = buf + 2 * COMPB, Bl = buf + 3 * COMPB;
#pragma unroll
        for (int ks = 0; ks < 2; ks++) {
            const uint32_t kbo = (uint32_t)(ks * 32);   // byte offset of k16 step
            uint32_t ah[4][4], al[4][4];
#pragma unroll
            for (int mt = 0; mt < 4; mt++) {
                uint32_t off = (uint32_t)((warp_m + mt * 16 + a_r) * PITCHB) + kbo + a_h * 16;
                ldm_x4(Ah + off, ah[mt][0], ah[mt][1], ah[mt][2], ah[mt][3]);
                ldm_x4(Al + off, al[mt][0], al[mt][1], al[mt][2], al[mt][3]);
            }
            uint32_t bhf[2][4], blf[2][4];
#pragma unroll
            for (int pr = 0; pr < 2; pr++) {
                uint32_t off = (uint32_t)((warp_n + pr * 16 + b_r) * PITCHB) + kbo + b_h * 16;
                ldm_x4(Bh + off, bhf[pr][0], bhf[pr][1], bhf[pr][2], bhf[pr][3]);
                ldm_x4(Bl + off, blf[pr][0], blf[pr][1], blf[pr][2], blf[pr][3]);
            }
#pragma unroll
            for (int mt = 0; mt < 4; mt++)
#pragma unroll
                for (int nt = 0; nt < 4; nt++) {
                    const int pr = nt >> 1, hf = (nt & 1) * 2;
                    mma_bf16_16x8x16(acc[mt][nt], ah[mt][0], ah[mt][1], ah[mt][2], ah[mt][3],
                                     bhf[pr][hf], bhf[pr][hf + 1]);
                    mma_bf16_16x8x16(acc[mt][nt], ah[mt][0], ah[mt][1], ah[mt][2], ah[mt][3],
                                     blf[pr][hf], blf[pr][hf + 1]);
                    mma_bf16_16x8x16(acc[mt][nt], al[mt][0], al[mt][1], al[mt][2], al[mt][3],
                                     bhf[pr][hf], bhf[pr][hf + 1]);
                }
        }
        __syncthreads();
    }

    // epilogue (m16n8 C layout)
    const int g = lane >> 2, t = lane & 3;
#pragma unroll
    for (int mt = 0; mt < 4; mt++) {
        int r0 = brow + warp_m + mt * 16 + g;
#pragma unroll
        for (int nt = 0; nt < 4; nt++) {
            int c0 = bcol + warp_n + nt * 8 + t * 2;
            float2* p0 = (float2*)(C + (size_t)r0 * N + c0);
            float2* p1 = (float2*)(C + (size_t)(r0 + 8) * N + c0);
            float2 v0 = make_float2(acc[mt][nt][0], acc[mt][nt][1]);
            float2 v1 = make_float2(acc[mt][nt][2], acc[mt][nt][3]);
            if (ACC) {
                float2 o0 = *p0, o1 = *p1;
                v0.x += o0.x; v0.y += o0.y;
                v1.x += o1.x; v1.y += o1.y;
            }
            *p0 = v0;
            *p1 = v1;
        }
    }
}

// ------------- weight transpose+split: [K,N] fp32 -> [N,K] bf16 hi/lo -------
__global__ void transpose_split_kernel(const float* __restrict__ in,
                                       uint16_t* __restrict__ hi,
                                       uint16_t* __restrict__ lo, int K, int N) {
    __shared__ float tile[32][33];
    int kx = blockIdx.x * 32, ny = blockIdx.y * 32;
    int tx = threadIdx.x, ty = threadIdx.y;
#pragma unroll
    for (int r = ty; r < 32; r += 8)
        tile[r][tx] = in[(size_t)(kx + r) * N + ny + tx];
    __syncthreads();
#pragma unroll
    for (int r = ty; r < 32; r += 8)
        split_w(hi, lo, (size_t)(ny + r) * K + kx + tx, tile[tx][r]);
}

// ------------- elementwise split (embed table) ------------------------------
__global__ void split4_kernel(const float4* __restrict__ in,
                              uint2* __restrict__ hi, uint2* __restrict__ lo, int n4) {
    int i = blockIdx.x * blockDim.x + threadIdx.x;
    if (i >= n4) return;
    float4 v = in[i];
    __nv_bfloat16 h0 = __float2bfloat16_rn(v.x), h1 = __float2bfloat16_rn(v.y);
    __nv_bfloat16 h2 = __float2bfloat16_rn(v.z), h3 = __float2bfloat16_rn(v.w);
    __nv_bfloat16 l0 = __float2bfloat16_rn(v.x - __bfloat162float(h0));
    __nv_bfloat16 l1 = __float2bfloat16_rn(v.y - __bfloat162float(h1));
    __nv_bfloat16 l2 = __float2bfloat16_rn(v.z - __bfloat162float(h2));
    __nv_bfloat16 l3 = __float2bfloat16_rn(v.w - __bfloat162float(h3));
    hi[i] = make_uint2((uint32_t)bfbits(h0) | ((uint32_t)bfbits(h1) << 16),
                       (uint32_t)bfbits(h2) | ((uint32_t)bfbits(h3) << 16));
    lo[i] = make_uint2((uint32_t)bfbits(l0) | ((uint32_t)bfbits(l1) << 16),
                       (uint32_t)bfbits(l2) | ((uint32_t)bfbits(l3) << 16));
}

// ---------------- embedding gather ----------------------------------------
__global__ void embed_kernel(const int* __restrict__ tokens,
                             const float* __restrict__ embed,
                             float* __restrict__ x) {
    int m = blockIdx.x;
    int tkn = tokens[m];
    const float4* src = (const float4*)(embed + (size_t)tkn * D_);
    float4*       dst = (float4*)(x + (size_t)m * D_);
    for (int i = threadIdx.x; i < D_ / 4; i += blockDim.x) dst[i] = src[i];
}

// ---------------- RMSNorm -> split bf16 output ------------------------------
__global__ void rmsnorm_split_kernel(const float* __restrict__ x,
                                     const float* __restrict__ w,
                                     uint16_t* __restrict__ hi,
                                     uint16_t* __restrict__ lo) {
    int m = blockIdx.x;
    const float* xr = x + (size_t)m * D_;
    float ss = 0.f;
    for (int i = threadIdx.x; i < D_; i += 256) { float v = xr[i]; ss += v * v; }
    ss += __shfl_xor_sync(0xffffffffu, ss, 16);
    ss += __shfl_xor_sync(0xffffffffu, ss, 8);
    ss += __shfl_xor_sync(0xffffffffu, ss, 4);
    ss += __shfl_xor_sync(0xffffffffu, ss, 2);
    ss += __shfl_xor_sync(0xffffffffu, ss, 1);
    __shared__ float red[8];
    int wid = threadIdx.x >> 5, lane = threadIdx.x & 31;
    if (lane == 0) red[wid] = ss;
    __syncthreads();
    float tot = red[0] + red[1] + red[2] + red[3] + red[4] + red[5] + red[6] + red[7];
    float rn = rsqrtf(tot / (float)D_ + 1e-6f);
    for (int i = threadIdx.x; i < D_; i += 256)
        split_w(hi, lo, (size_t)m * D_ + i, xr[i] * rn * w[i]);
}

// ---------------- RoPE (in place, pairs (i, i+32) per thread) ---------------
__global__ void rope_kernel(float* __restrict__ x, int nheads, int total) {
    int idx = blockIdx.x * blockDim.x + threadIdx.x;
    if (idx >= total) return;
    int i    = idx & 31;
    int head = (idx >> 5) % nheads;
    int m    = idx / (32 * nheads);
    int s    = m % S_;
    float inv_freq = expf(-(float)(2 * i) * (1.0f / 64.0f) * 9.210340371976184f);
    float ang = (float)s * inv_freq;
    float sn, cs;
    sincosf(ang, &sn, &cs);
    float* base = x + (size_t)m * (nheads * HD_) + head * HD_;
    float x1 = base[i];
    float x2 = base[i + 32];
    base[i]      = x1 * cs - x2 * sn;
    base[i + 32] = x2 * cs + x1 * sn;
}

// -------- causal attention (warp per query row), split bf16 output ----------
__global__ void attn_kernel(const float* __restrict__ q,
                            const float* __restrict__ k,
                            const float* __restrict__ v,
                            uint16_t* __restrict__ out_hi,
                            uint16_t* __restrict__ out_lo) {
    int bh   = blockIdx.x;
    int b    = bh / H_;
    int h    = bh % H_;
    int gq   = h / NREP_;
    int warp = threadIdx.x >> 5;
    int lane = threadIdx.x & 31;
    int s    = blockIdx.y * 8 + warp;

    const float2* qp = (const float2*)(q + (size_t)(b * S_ + s) * QW_ + h * HD_);
    float2 qv = qp[lane];
    const float* kbase = k + (size_t)b * S_ * KVW_ + gq * HD_;
    const float* vbase = v + (size_t)b * S_ * KVW_ + gq * HD_;

    float mx = -INFINITY, l = 0.f, a0 = 0.f, a1 = 0.f;
    const float inv_scale = 0.125f;

    for (int j = 0; j <= s; j++) {
        float2 kv2 = *(const float2*)(kbase + (size_t)j * KVW_ + lane * 2);
        float p = qv.x * kv2.x + qv.y * kv2.y;
        p += __shfl_xor_sync(0xffffffffu, p, 16);
        p += __shfl_xor_sync(0xffffffffu, p, 8);
        p += __shfl_xor_sync(0xffffffffu, p, 4);
        p += __shfl_xor_sync(0xffffffffu, p, 2);
        p += __shfl_xor_sync(0xffffffffu, p, 1);
        float sc = p * inv_scale;
        float mn = fmaxf(mx, sc);
        float corr = __expf(mx - mn);
        float pe   = __expf(sc - mn);
        l = l * corr + pe;
        float2 vv = *(const float2*)(vbase + (size_t)j * KVW_ + lane * 2);
        a0 = a0 * corr + pe * vv.x;
        a1 = a1 * corr + pe * vv.y;
        mx = mn;
    }
    float invl = 1.f / l;
    size_t base_idx = (size_t)(b * S_ + s) * QW_ + h * HD_ + lane * 2;
    split_w(out_hi, out_lo, base_idx,     a0 * invl);
    split_w(out_hi, out_lo, base_idx + 1, a1 * invl);
}

// ---------------- SiLU(gate) * up -> split bf16 -----------------------------
__global__ void silumul_split_kernel(const float* __restrict__ gate,
                                     const float* __restrict__ up,
                                     uint16_t* __restrict__ hi,
                                     uint16_t* __restrict__ lo, int n) {
    int idx = blockIdx.x * blockDim.x + threadIdx.x;
    if (idx >= n) return;
    float gv = gate[idx];
    float sig = 1.f / (1.f + __expf(-gv));
    split_w(hi, lo, idx, gv * sig * up[idx]);
}

// ---------------- driver ----------------------------------------------------
extern "C" void kernel_launch(void* const* d_in, const int* in_sizes, int n_in,
                              void* d_out, int out_size) {
    const int*   tokens     = (const int*)d_in[0];
    const float* embed      = (const float*)d_in[1];
    const float* wq         = (const float*)d_in[2];
    const float* wk         = (const float*)d_in[3];
    const float* wv         = (const float*)d_in[4];
    const float* wo         = (const float*)d_in[5];
    const float* w_gate     = (const float*)d_in[6];
    const float* w_up       = (const float*)d_in[7];
    const float* w_down     = (const float*)d_in[8];
    const float* norm1_w    = (const float*)d_in[9];
    const float* norm2_w    = (const float*)d_in[10];
    const float* final_norm = (const float*)d_in[11];
    float* out = (float*)d_out;

    float *x, *q, *k, *v, *gate, *up;
    uint16_t *h_hi, *h_lo, *att_hi, *att_lo, *gs_hi, *gs_lo;
    uint16_t *wqt_hi, *wqt_lo, *wkt_hi, *wkt_lo, *wvt_hi, *wvt_lo;
    uint16_t *wot_hi, *wot_lo, *wgt_hi, *wgt_lo, *wut_hi, *wut_lo, *wdt_hi, *wdt_lo;
    uint16_t *emb_hi, *emb_lo;
    cudaGetSymbolAddress((void**)&x,    g_x);
    cudaGetSymbolAddress((void**)&q,    g_q);
    cudaGetSymbolAddress((void**)&k,    g_k);
    cudaGetSymbolAddress((void**)&v,    g_v);
    cudaGetSymbolAddress((void**)&gate, g_gate);
    cudaGetSymbolAddress((void**)&up,   g_up);
    cudaGetSymbolAddress((void**)&h_hi,   g_h_hi);
    cudaGetSymbolAddress((void**)&h_lo,   g_h_lo);
    cudaGetSymbolAddress((void**)&att_hi, g_att_hi);
    cudaGetSymbolAddress((void**)&att_lo, g_att_lo);
    cudaGetSymbolAddress((void**)&gs_hi,  g_gs_hi);
    cudaGetSymbolAddress((void**)&gs_lo,  g_gs_lo);
    cudaGetSymbolAddress((void**)&wqt_hi, g_wqt_hi);
    cudaGetSymbolAddress((void**)&wqt_lo, g_wqt_lo);
    cudaGetSymbolAddress((void**)&wkt_hi, g_wkt_hi);
    cudaGetSymbolAddress((void**)&wkt_lo, g_wkt_lo);
    cudaGetSymbolAddress((void**)&wvt_hi, g_wvt_hi);
    cudaGetSymbolAddress((void**)&wvt_lo, g_wvt_lo);
    cudaGetSymbolAddress((void**)&wot_hi, g_wot_hi);
    cudaGetSymbolAddress((void**)&wot_lo, g_wot_lo);
    cudaGetSymbolAddress((void**)&wgt_hi, g_wgt_hi);
    cudaGetSymbolAddress((void**)&wgt_lo, g_wgt_lo);
    cudaGetSymbolAddress((void**)&wut_hi, g_wut_hi);
    cudaGetSymbolAddress((void**)&wut_lo, g_wut_lo);
    cudaGetSymbolAddress((void**)&wdt_hi, g_wdt_hi);
    cudaGetSymbolAddress((void**)&wdt_lo, g_wdt_lo);
    cudaGetSymbolAddress((void**)&emb_hi, g_emb_hi);
    cudaGetSymbolAddress((void**)&emb_lo, g_emb_lo);

    cudaFuncSetAttribute(bf16x3_gemm<false>,
                         cudaFuncAttributeMaxDynamicSharedMemorySize, GEMM_SMEM_BYTES);
    cudaFuncSetAttribute(bf16x3_gemm<true>,
                         cudaFuncAttributeMaxDynamicSharedMemorySize, GEMM_SMEM_BYTES);

    embed_kernel<<<M_, 256>>>(tokens, embed, x);
    split4_kernel<<<(V_ * D_ / 4 + 255) / 256, 256>>>((const float4*)embed,
                                                      (uint2*)emb_hi, (uint2*)emb_lo,
                                                      V_ * D_ / 4);

    dim3 t32(32, 8);
    for (int i = 0; i < L_; i++) {
        const float* wqi = wq + (size_t)i * D_ * QW_;
        const float* wki = wk + (size_t)i * D_ * KVW_;
        const float* wvi = wv + (size_t)i * D_ * KVW_;
        const float* woi = wo + (size_t)i * QW_ * D_;
        const float* wgi = w_gate + (size_t)i * D_ * FF_;
        const float* wui = w_up   + (size_t)i * D_ * FF_;
        const float* wdi = w_down + (size_t)i * FF_ * D_;

        transpose_split_kernel<<<dim3(D_ / 32, QW_ / 32),  t32>>>(wqi, wqt_hi, wqt_lo, D_, QW_);
        transpose_split_kernel<<<dim3(D_ / 32, KVW_ / 32), t32>>>(wki, wkt_hi, wkt_lo, D_, KVW_);
        transpose_split_kernel<<<dim3(D_ / 32, KVW_ / 32), t32>>>(wvi, wvt_hi, wvt_lo, D_, KVW_);
        transpose_split_kernel<<<dim3(QW_ / 32, D_ / 32),  t32>>>(woi, wot_hi, wot_lo, QW_, D_);
        transpose_split_kernel<<<dim3(D_ / 32, FF_ / 32),  t32>>>(wgi, wgt_hi, wgt_lo, D_, FF_);
        transpose_split_kernel<<<dim3(D_ / 32, FF_ / 32),  t32>>>(wui, wut_hi, wut_lo, D_, FF_);
        transpose_split_kernel<<<dim3(FF_ / 32, D_ / 32),  t32>>>(wdi, wdt_hi, wdt_lo, FF_, D_);

        rmsnorm_split_kernel<<<M_, 256>>>(x, norm1_w + (size_t)i * D_, h_hi, h_lo);

        bf16x3_gemm<false><<<dim3(QW_ / 128, M_ / 128), 256, GEMM_SMEM_BYTES>>>(
            h_hi, h_lo, wqt_hi, wqt_lo, q, M_, QW_, D_);
        bf16x3_gemm<false><<<dim3(KVW_ / 128, M_ / 128), 256, GEMM_SMEM_BYTES>>>(
            h_hi, h_lo, wkt_hi, wkt_lo, k, M_, KVW_, D_);
        bf16x3_gemm<false><<<dim3(KVW_ / 128, M_ / 128), 256, GEMM_SMEM_BYTES>>>(
            h_hi, h_lo, wvt_hi, wvt_lo, v, M_, KVW_, D_);

        rope_kernel<<<(M_ * H_ * 32 + 255) / 256, 256>>>(q, H_,   M_ * H_ * 32);
        rope_kernel<<<(M_ * HKV_ * 32 + 255) / 256, 256>>>(k, HKV_, M_ * HKV_ * 32);

        attn_kernel<<<dim3(B_ * H_, S_ / 8), 256>>>(q, k, v, att_hi, att_lo);

        bf16x3_gemm<true><<<dim3(D_ / 128, M_ / 128), 256, GEMM_SMEM_BYTES>>>(
            att_hi, att_lo, wot_hi, wot_lo, x, M_, D_, QW_);

        rmsnorm_split_kernel<<<M_, 256>>>(x, norm2_w + (size_t)i * D_, h_hi, h_lo);

        bf16x3_gemm<false><<<dim3(FF_ / 128, M_ / 128), 256, GEMM_SMEM_BYTES>>>(
            h_hi, h_lo, wgt_hi, wgt_lo, gate, M_, FF_, D_);
        bf16x3_gemm<false><<<dim3(FF_ / 128, M_ / 128), 256, GEMM_SMEM_BYTES>>>(
            h_hi, h_lo, wut_hi, wut_lo, up, M_, FF_, D_);

        silumul_split_kernel<<<(M_ * FF_ + 255) / 256, 256>>>(gate, up, gs_hi, gs_lo, M_ * FF_);

        bf16x3_gemm<true><<<dim3(D_ / 128, M_ / 128), 256, GEMM_SMEM_BYTES>>>(
            gs_hi, gs_lo, wdt_hi, wdt_lo, x, M_, D_, FF_);
    }

    rmsnorm_split_kernel<<<M_, 256>>>(x, final_norm, h_hi, h_lo);

    // logits = h @ embed^T ; embed is [V, D] = [N, K] row-major already
    bf16x3_gemm<false><<<dim3(V_ / 128, M_ / 128), 256, GEMM_SMEM_BYTES>>>(
        h_hi, h_lo, emb_hi, emb_lo, out, M_, V_, D_);
}

// round 12
// speedup vs baseline: 2.3025x; 1.0238x over previous
#include <cuda_runtime.h>
#include <cuda_bf16.h>
#include <math.h>
#include <stdint.h>

// Problem constants
#define V_   32000
#define D_   1024
#define H_   16
#define HKV_ 4
#define FF_  4096
#define L_   8
#define HD_  64
#define NREP_ 4
#define B_   2
#define S_   1024
#define M_   (B_*S_)      // 2048 tokens
#define KVW_ (HKV_*HD_)   // 256
#define QW_  (H_*HD_)     // 1024
#define QKVW_ (QW_ + 2*KVW_)   // 1536
#define GUW_  (2*FF_)          // 8192

// ---------------- scratch (device globals; no allocation allowed) ----------
__device__ float g_x   [M_*D_];
__device__ float g_qkv [M_*QKVW_];
__device__ float g_gu  [M_*GUW_];
// split (hi/lo bf16) activations
__device__ __align__(16) uint16_t g_h_hi  [M_*D_],  g_h_lo  [M_*D_];
__device__ __align__(16) uint16_t g_att_hi[M_*QW_], g_att_lo[M_*QW_];
__device__ __align__(16) uint16_t g_gs_hi [M_*FF_], g_gs_lo [M_*FF_];
// split transposed weights for ALL layers ([N,K] row-major per layer)
__device__ __align__(16) uint16_t g_wqkvt_hi[L_*QKVW_*D_], g_wqkvt_lo[L_*QKVW_*D_];
__device__ __align__(16) uint16_t g_wot_hi  [L_*D_*QW_],   g_wot_lo  [L_*D_*QW_];
__device__ __align__(16) uint16_t g_wgut_hi [L_*GUW_*D_],  g_wgut_lo [L_*GUW_*D_];
__device__ __align__(16) uint16_t g_wdt_hi  [L_*D_*FF_],   g_wdt_lo  [L_*D_*FF_];
// split embed table (for logits GEMM B operand)
__device__ __align__(16) uint16_t g_emb_hi[V_*D_], g_emb_lo[V_*D_];

// ---------------- helpers ---------------------------------------------------
__device__ __forceinline__ uint32_t smem_u32(const void* p) {
    uint32_t a;
    asm("{ .reg .u64 t; cvta.to.shared.u64 t, %1; cvt.u32.u64 %0, t; }"
        : "=r"(a) : "l"(p));
    return a;
}
__device__ __forceinline__ uint16_t bfbits(__nv_bfloat16 h) {
    return *reinterpret_cast<uint16_t*>(&h);
}
__device__ __forceinline__ void split_w(uint16_t* hi, uint16_t* lo, size_t idx, float v) {
    __nv_bfloat16 hb = __float2bfloat16_rn(v);
    float l = v - __bfloat162float(hb);
    __nv_bfloat16 lb = __float2bfloat16_rn(l);
    hi[idx] = bfbits(hb);
    lo[idx] = bfbits(lb);
}

#define CP_A16(s, g) asm volatile("cp.async.cg.shared.global [%0], [%1], 16;" :: "r"(s), "l"(g))
#define CP_COMMIT()  asm volatile("cp.async.commit_group;" ::: "memory")
#define CP_WAIT1()   asm volatile("cp.async.wait_group 1;" ::: "memory")
#define CP_WAIT0()   asm volatile("cp.async.wait_group 0;" ::: "memory")

__device__ __forceinline__ void ldm_x4(uint32_t a, uint32_t& r0, uint32_t& r1,
                                       uint32_t& r2, uint32_t& r3) {
    asm volatile("ldmatrix.sync.aligned.m8n8.x4.shared.b16 {%0,%1,%2,%3}, [%4];"
                 : "=r"(r0), "=r"(r1), "=r"(r2), "=r"(r3) : "r"(a));
}

__device__ __forceinline__ void mma_bf16_16x8x16(float* c, uint32_t a0, uint32_t a1,
                                                 uint32_t a2, uint32_t a3,
                                                 uint32_t b0, uint32_t b1) {
    asm volatile(
        "mma.sync.aligned.m16n8k16.row.col.f32.bf16.bf16.f32 "
        "{%0,%1,%2,%3}, {%4,%5,%6,%7}, {%8,%9}, {%0,%1,%2,%3};"
        : "+f"(c[0]), "+f"(c[1]), "+f"(c[2]), "+f"(c[3])
        : "r"(a0), "r"(a1), "r"(a2), "r"(a3), "r"(b0), "r"(b1));
}

// ================= bf16x3 split GEMM (NT), pre-split operands ==============
// C[M,N] = (ACC ? C : 0) + (Ahi+Alo)[M,K] * (Bhi+Blo)[N,K]^T  (drop lo*lo).
// CTA tile 128x128, BK=32, 256 threads (8 warps, warp tile 64x32).
// 3-stage cp.async ring, ONE __syncthreads per K-iter.
#define PITCHB 80
#define COMPB  (128 * PITCHB)     // 10240 B per component
#define BUFB   (4 * COMPB)        // 40960 B per stage
#define NSTAGE 3
#define GEMM_SMEM_BYTES (NSTAGE * BUFB)   // 122880 B

__device__ __forceinline__ void issue_tile(uint32_t sbuf,
    const uint16_t* Ahi, const uint16_t* Alo,
    const uint16_t* Bhi, const uint16_t* Blo,
    int brow, int bcol, int K, int k0, int tid)
{
#pragma unroll
    for (int c = 0; c < 2; c++) {
        int idx = tid + c * 256;
        int row = idx >> 2;
        int co  = (idx & 3) * 8;
        uint32_t so = (uint32_t)(row * PITCHB + co * 2);
        size_t goA = (size_t)(brow + row) * K + k0 + co;
        size_t goB = (size_t)(bcol + row) * K + k0 + co;
        CP_A16(sbuf + so,             Ahi + goA);
        CP_A16(sbuf + COMPB + so,     Alo + goA);
        CP_A16(sbuf + 2 * COMPB + so, Bhi + goB);
        CP_A16(sbuf + 3 * COMPB + so, Blo + goB);
    }
    CP_COMMIT();
}

template <bool ACC>
__global__ __launch_bounds__(256)
void bf16x3_gemm(const uint16_t* __restrict__ Ahi, const uint16_t* __restrict__ Alo,
                 const uint16_t* __restrict__ Bhi, const uint16_t* __restrict__ Blo,
                 float* __restrict__ C, int M, int N, int K) {
    extern __shared__ char smem[];
    const uint32_t sb = smem_u32(smem);
    const int tid    = threadIdx.x;
    const int wid    = tid >> 5;
    const int lane   = tid & 31;
    const int warp_m = (wid & 1) * 64;
    const int warp_n = (wid >> 1) * 32;
    const int brow   = blockIdx.y * 128;
    const int bcol   = blockIdx.x * 128;

    float acc[4][4][4];
#pragma unroll
    for (int i = 0; i < 4; i++)
#pragma unroll
        for (int j = 0; j < 4; j++)
#pragma unroll
            for (int r = 0; r < 4; r++) acc[i][j][r] = 0.f;

    const int niter = K >> 5;

    // prologue: stage 0,1
    issue_tile(sb,        Ahi, Alo, Bhi, Blo, brow, bcol, K, 0,  tid);
    issue_tile(sb + BUFB, Ahi, Alo, Bhi, Blo, brow, bcol, K, 32, tid);

    const int a_r = lane & 15;
    const int a_h = (lane >> 4) & 1;
    const int b_r = ((lane >> 4) & 1) * 8 + (lane & 7);
    const int b_h = (lane >> 3) & 1;

    int s_cur = 0;   // slot of tile `it`
    int s_nxt = 2;   // slot for tile `it+2`
    for (int it = 0; it < niter; it++) {
        if (it + 1 < niter) CP_WAIT1(); else CP_WAIT0();
        __syncthreads();
        if (it + 2 < niter)
            issue_tile(sb + (uint32_t)s_nxt * BUFB, Ahi, Alo, Bhi, Blo,
                       brow, bcol, K, (it + 2) << 5, tid);

        const uint32_t buf = sb + (uint32_t)s_cur * BUFB;
        const uint32_t Ah = buf, Al = buf + COMPB, Bh = buf + 2 * COMPB, Bl = buf + 3 * COMPB;
#pragma unroll
        for (int ks = 0; ks < 2; ks++) {
            const uint32_t kbo = (uint32_t)(ks * 32);
            uint32_t ah[4][4], al[4][4];
#pragma unroll
            for (int mt = 0; mt < 4; mt++) {
                uint32_t off = (uint32_t)((warp_m + mt * 16 + a_r) * PITCHB) + kbo + a_h * 16;
                ldm_x4(Ah + off, ah[mt][0], ah[mt][1], ah[mt][2], ah[mt][3]);
                ldm_x4(Al + off, al[mt][0], al[mt][1], al[mt][2], al[mt][3]);
            }
            uint32_t bhf[2][4], blf[2][4];
#pragma unroll
            for (int pr = 0; pr < 2; pr++) {
                uint32_t off = (uint32_t)((warp_n + pr * 16 + b_r) * PITCHB) + kbo + b_h * 16;
                ldm_x4(Bh + off, bhf[pr][0], bhf[pr][1], bhf[pr][2], bhf[pr][3]);
                ldm_x4(Bl + off, blf[pr][0], blf[pr][1], blf[pr][2], blf[pr][3]);
            }
#pragma unroll
            for (int mt = 0; mt < 4; mt++)
#pragma unroll
                for (int nt = 0; nt < 4; nt++) {
                    const int pr = nt >> 1, hf = (nt & 1) * 2;
                    mma_bf16_16x8x16(acc[mt][nt], ah[mt][0], ah[mt][1], ah[mt][2], ah[mt][3],
                                     bhf[pr][hf], bhf[pr][hf + 1]);
                    mma_bf16_16x8x16(acc[mt][nt], ah[mt][0], ah[mt][1], ah[mt][2], ah[mt][3],
                                     blf[pr][hf], blf[pr][hf + 1]);
                    mma_bf16_16x8x16(acc[mt][nt], al[mt][0], al[mt][1], al[mt][2], al[mt][3],
                                     bhf[pr][hf], bhf[pr][hf + 1]);
                }
        }
        s_cur = (s_cur == NSTAGE - 1) ? 0 : s_cur + 1;
        s_nxt = (s_nxt == NSTAGE - 1) ? 0 : s_nxt + 1;
    }

    // epilogue (m16n8 C layout)
    const int g = lane >> 2, t = lane & 3;
#pragma unroll
    for (int mt = 0; mt < 4; mt++) {
        int r0 = brow + warp_m + mt * 16 + g;
#pragma unroll
        for (int nt = 0; nt < 4; nt++) {
            int c0 = bcol + warp_n + nt * 8 + t * 2;
            float2* p0 = (float2*)(C + (size_t)r0 * N + c0);
            float2* p1 = (float2*)(C + (size_t)(r0 + 8) * N + c0);
            float2 v0 = make_float2(acc[mt][nt][0], acc[mt][nt][1]);
            float2 v1 = make_float2(acc[mt][nt][2], acc[mt][nt][3]);
            if (ACC) {
                float2 o0 = *p0, o1 = *p1;
                v0.x += o0.x; v0.y += o0.y;
                v1.x += o1.x; v1.y += o1.y;
            }
            *p0 = v0;
            *p1 = v1;
        }
    }
}

// ----- batched weight transpose+split: [K,N] fp32 -> [N,K] bf16 hi/lo -------
// blockIdx.z = layer; hi/lo already offset to the target row block.
__global__ void transpose_split_batched(const float* __restrict__ in,
                                        uint16_t* __restrict__ hi,
                                        uint16_t* __restrict__ lo,
                                        int K, int N,
                                        size_t in_lstride, size_t out_lstride) {
    __shared__ float tile[32][33];
    int z = blockIdx.z;
    in += (size_t)z * in_lstride;
    hi += (size_t)z * out_lstride;
    lo += (size_t)z * out_lstride;
    int kx = blockIdx.x * 32, ny = blockIdx.y * 32;
    int tx = threadIdx.x, ty = threadIdx.y;
#pragma unroll
    for (int r = ty; r < 32; r += 8)
        tile[r][tx] = in[(size_t)(kx + r) * N + ny + tx];
    __syncthreads();
#pragma unroll
    for (int r = ty; r < 32; r += 8)
        split_w(hi, lo, (size_t)(ny + r) * K + kx + tx, tile[tx][r]);
}

// ------------- elementwise split (embed table) ------------------------------
__global__ void split4_kernel(const float4* __restrict__ in,
                              uint2* __restrict__ hi, uint2* __restrict__ lo, int n4) {
    int i = blockIdx.x * blockDim.x + threadIdx.x;
    if (i >= n4) return;
    float4 v = in[i];
    __nv_bfloat16 h0 = __float2bfloat16_rn(v.x), h1 = __float2bfloat16_rn(v.y);
    __nv_bfloat16 h2 = __float2bfloat16_rn(v.z), h3 = __float2bfloat16_rn(v.w);
    __nv_bfloat16 l0 = __float2bfloat16_rn(v.x - __bfloat162float(h0));
    __nv_bfloat16 l1 = __float2bfloat16_rn(v.y - __bfloat162float(h1));
    __nv_bfloat16 l2 = __float2bfloat16_rn(v.z - __bfloat162float(h2));
    __nv_bfloat16 l3 = __float2bfloat16_rn(v.w - __bfloat162float(h3));
    hi[i] = make_uint2((uint32_t)bfbits(h0) | ((uint32_t)bfbits(h1) << 16),
                       (uint32_t)bfbits(h2) | ((uint32_t)bfbits(h3) << 16));
    lo[i] = make_uint2((uint32_t)bfbits(l0) | ((uint32_t)bfbits(l1) << 16),
                       (uint32_t)bfbits(l2) | ((uint32_t)bfbits(l3) << 16));
}

// ---------------- embedding gather ----------------------------------------
__global__ void embed_kernel(const int* __restrict__ tokens,
                             const float* __restrict__ embed,
                             float* __restrict__ x) {
    int m = blockIdx.x;
    int tkn = tokens[m];
    const float4* src = (const float4*)(embed + (size_t)tkn * D_);
    float4*       dst = (float4*)(x + (size_t)m * D_);
    for (int i = threadIdx.x; i < D_ / 4; i += blockDim.x) dst[i] = src[i];
}

// ---------------- RMSNorm -> split bf16 output ------------------------------
__global__ void rmsnorm_split_kernel(const float* __restrict__ x,
                                     const float* __restrict__ w,
                                     uint16_t* __restrict__ hi,
                                     uint16_t* __restrict__ lo) {
    int m = blockIdx.x;
    const float* xr = x + (size_t)m * D_;
    float ss = 0.f;
    for (int i = threadIdx.x; i < D_; i += 256) { float v = xr[i]; ss += v * v; }
    ss += __shfl_xor_sync(0xffffffffu, ss, 16);
    ss += __shfl_xor_sync(0xffffffffu, ss, 8);
    ss += __shfl_xor_sync(0xffffffffu, ss, 4);
    ss += __shfl_xor_sync(0xffffffffu, ss, 2);
    ss += __shfl_xor_sync(0xffffffffu, ss, 1);
    __shared__ float red[8];
    int wid = threadIdx.x >> 5, lane = threadIdx.x & 31;
    if (lane == 0) red[wid] = ss;
    __syncthreads();
    float tot = red[0] + red[1] + red[2] + red[3] + red[4] + red[5] + red[6] + red[7];
    float rn = rsqrtf(tot / (float)D_ + 1e-6f);
    for (int i = threadIdx.x; i < D_; i += 256)
        split_w(hi, lo, (size_t)m * D_ + i, xr[i] * rn * w[i]);
}

// ---------------- RoPE (in place, pairs (i, i+32) per thread) ---------------
__global__ void rope_kernel(float* __restrict__ x, int nheads, int rowstride, int total) {
    int idx = blockIdx.x * blockDim.x + threadIdx.x;
    if (idx >= total) return;
    int i    = idx & 31;
    int head = (idx >> 5) % nheads;
    int m    = idx / (32 * nheads);
    int s    = m % S_;
    float inv_freq = expf(-(float)(2 * i) * (1.0f / 64.0f) * 9.210340371976184f);
    float ang = (float)s * inv_freq;
    float sn, cs;
    sincosf(ang, &sn, &cs);
    float* base = x + (size_t)m * rowstride + head * HD_;
    float x1 = base[i];
    float x2 = base[i + 32];
    base[i]      = x1 * cs - x2 * sn;
    base[i + 32] = x2 * cs + x1 * sn;
}

// -------- causal attention (warp per query row), reads fused qkv ------------
__global__ void attn_kernel(const float* __restrict__ qkv,
                            uint16_t* __restrict__ out_hi,
                            uint16_t* __restrict__ out_lo) {
    int bh   = blockIdx.x;
    int b    = bh / H_;
    int h    = bh % H_;
    int gq   = h / NREP_;
    int warp = threadIdx.x >> 5;
    int lane = threadIdx.x & 31;
    int s    = blockIdx.y * 8 + warp;

    const float2* qp = (const float2*)(qkv + (size_t)(b * S_ + s) * QKVW_ + h * HD_);
    float2 qv = qp[lane];
    const float* kbase = qkv + (size_t)b * S_ * QKVW_ + QW_ + gq * HD_;
    const float* vbase = qkv + (size_t)b * S_ * QKVW_ + QW_ + KVW_ + gq * HD_;

    float mx = -INFINITY, l = 0.f, a0 = 0.f, a1 = 0.f;
    const float inv_scale = 0.125f;

    for (int j = 0; j <= s; j++) {
        float2 kv2 = *(const float2*)(kbase + (size_t)j * QKVW_ + lane * 2);
        float p = qv.x * kv2.x + qv.y * kv2.y;
        p += __shfl_xor_sync(0xffffffffu, p, 16);
        p += __shfl_xor_sync(0xffffffffu, p, 8);
        p += __shfl_xor_sync(0xffffffffu, p, 4);
        p += __shfl_xor_sync(0xffffffffu, p, 2);
        p += __shfl_xor_sync(0xffffffffu, p, 1);
        float sc = p * inv_scale;
        float mn = fmaxf(mx, sc);
        float corr = __expf(mx - mn);
        float pe   = __expf(sc - mn);
        l = l * corr + pe;
        float2 vv = *(const float2*)(vbase + (size_t)j * QKVW_ + lane * 2);
        a0 = a0 * corr + pe * vv.x;
        a1 = a1 * corr + pe * vv.y;
        mx = mn;
    }
    float invl = 1.f / l;
    size_t base_idx = (size_t)(b * S_ + s) * QW_ + h * HD_ + lane * 2;
    split_w(out_hi, out_lo, base_idx,     a0 * invl);
    split_w(out_hi, out_lo, base_idx + 1, a1 * invl);
}

// ------- SiLU(gate)*up from fused gu buffer -> split bf16 -------------------
__global__ void silumul_split_kernel(const float* __restrict__ gu,
                                     uint16_t* __restrict__ hi,
                                     uint16_t* __restrict__ lo, int n) {
    int idx = blockIdx.x * blockDim.x + threadIdx.x;
    if (idx >= n) return;
    int m = idx >> 12;          // / FF_
    int j = idx & (FF_ - 1);
    float gv = gu[(size_t)m * GUW_ + j];
    float uv = gu[(size_t)m * GUW_ + FF_ + j];
    float sig = 1.f / (1.f + __expf(-gv));
    split_w(hi, lo, idx, gv * sig * uv);
}

// ---------------- driver ----------------------------------------------------
extern "C" void kernel_launch(void* const* d_in, const int* in_sizes, int n_in,
                              void* d_out, int out_size) {
    const int*   tokens     = (const int*)d_in[0];
    const float* embed      = (const float*)d_in[1];
    const float* wq         = (const float*)d_in[2];
    const float* wk         = (const float*)d_in[3];
    const float* wv         = (const float*)d_in[4];
    const float* wo         = (const float*)d_in[5];
    const float* w_gate     = (const float*)d_in[6];
    const float* w_up       = (const float*)d_in[7];
    const float* w_down     = (const float*)d_in[8];
    const float* norm1_w    = (const float*)d_in[9];
    const float* norm2_w    = (const float*)d_in[10];
    const float* final_norm = (const float*)d_in[11];
    float* out = (float*)d_out;

    float *x, *qkv, *gu;
    uint16_t *h_hi, *h_lo, *att_hi, *att_lo, *gs_hi, *gs_lo;
    uint16_t *wqkvt_hi, *wqkvt_lo, *wot_hi, *wot_lo, *wgut_hi, *wgut_lo, *wdt_hi, *wdt_lo;
    uint16_t *emb_hi, *emb_lo;
    cudaGetSymbolAddress((void**)&x,    g_x);
    cudaGetSymbolAddress((void**)&qkv,  g_qkv);
    cudaGetSymbolAddress((void**)&gu,   g_gu);
    cudaGetSymbolAddress((void**)&h_hi,   g_h_hi);
    cudaGetSymbolAddress((void**)&h_lo,   g_h_lo);
    cudaGetSymbolAddress((void**)&att_hi, g_att_hi);
    cudaGetSymbolAddress((void**)&att_lo, g_att_lo);
    cudaGetSymbolAddress((void**)&gs_hi,  g_gs_hi);
    cudaGetSymbolAddress((void**)&gs_lo,  g_gs_lo);
    cudaGetSymbolAddress((void**)&wqkvt_hi, g_wqkvt_hi);
    cudaGetSymbolAddress((void**)&wqkvt_lo, g_wqkvt_lo);
    cudaGetSymbolAddress((void**)&wot_hi,   g_wot_hi);
    cudaGetSymbolAddress((void**)&wot_lo,   g_wot_lo);
    cudaGetSymbolAddress((void**)&wgut_hi,  g_wgut_hi);
    cudaGetSymbolAddress((void**)&wgut_lo,  g_wgut_lo);
    cudaGetSymbolAddress((void**)&wdt_hi,   g_wdt_hi);
    cudaGetSymbolAddress((void**)&wdt_lo,   g_wdt_lo);
    cudaGetSymbolAddress((void**)&emb_hi,   g_emb_hi);
    cudaGetSymbolAddress((void**)&emb_lo,   g_emb_lo);

    cudaFuncSetAttribute(bf16x3_gemm<false>,
                         cudaFuncAttributeMaxDynamicSharedMemorySize, GEMM_SMEM_BYTES);
    cudaFuncSetAttribute(bf16x3_gemm<true>,
                         cudaFuncAttributeMaxDynamicSharedMemorySize, GEMM_SMEM_BYTES);

    embed_kernel<<<M_, 256>>>(tokens, embed, x);
    split4_kernel<<<(V_ * D_ / 4 + 255) / 256, 256>>>((const float4*)embed,
                                                      (uint2*)emb_hi, (uint2*)emb_lo,
                                                      V_ * D_ / 4);

    // ---- batched transposes for all layers (7 launches total) ----
    dim3 t32(32, 8);
    const size_t QKV_L = (size_t)QKVW_ * D_;
    const size_t GU_L  = (size_t)GUW_ * D_;
    transpose_split_batched<<<dim3(D_ / 32, QW_ / 32, L_), t32>>>(
        wq, wqkvt_hi, wqkvt_lo, D_, QW_, (size_t)D_ * QW_, QKV_L);
    transpose_split_batched<<<dim3(D_ / 32, KVW_ / 32, L_), t32>>>(
        wk, wqkvt_hi + (size_t)QW_ * D_, wqkvt_lo + (size_t)QW_ * D_,
        D_, KVW_, (size_t)D_ * KVW_, QKV_L);
    transpose_split_batched<<<dim3(D_ / 32, KVW_ / 32, L_), t32>>>(
        wv, wqkvt_hi + (size_t)(QW_ + KVW_) * D_, wqkvt_lo + (size_t)(QW_ + KVW_) * D_,
        D_, KVW_, (size_t)D_ * KVW_, QKV_L);
    transpose_split_batched<<<dim3(QW_ / 32, D_ / 32, L_), t32>>>(
        wo, wot_hi, wot_lo, QW_, D_, (size_t)QW_ * D_, (size_t)D_ * QW_);
    transpose_split_batched<<<dim3(D_ / 32, FF_ / 32, L_), t32>>>(
        w_gate, wgut_hi, wgut_lo, D_, FF_, (size_t)D_ * FF_, GU_L);
    transpose_split_batched<<<dim3(D_ / 32, FF_ / 32, L_), t32>>>(
        w_up, wgut_hi + (size_t)FF_ * D_, wgut_lo + (size_t)FF_ * D_,
        D_, FF_, (size_t)D_ * FF_, GU_L);
    transpose_split_batched<<<dim3(FF_ / 32, D_ / 32, L_), t32>>>(
        w_down, wdt_hi, wdt_lo, FF_, D_, (size_t)FF_ * D_, (size_t)D_ * FF_);

    for (int i = 0; i < L_; i++) {
        const uint16_t* wqkvt_hi_i = wqkvt_hi + (size_t)i * QKV_L;
        const uint16_t* wqkvt_lo_i = wqkvt_lo + (size_t)i * QKV_L;
        const uint16_t* wot_hi_i   = wot_hi + (size_t)i * D_ * QW_;
        const uint16_t* wot_lo_i   = wot_lo + (size_t)i * D_ * QW_;
        const uint16_t* wgut_hi_i  = wgut_hi + (size_t)i * GU_L;
        const uint16_t* wgut_lo_i  = wgut_lo + (size_t)i * GU_L;
        const uint16_t* wdt_hi_i   = wdt_hi + (size_t)i * D_ * FF_;
        const uint16_t* wdt_lo_i   = wdt_lo + (size_t)i * D_ * FF_;

        rmsnorm_split_kernel<<<M_, 256>>>(x, norm1_w + (size_t)i * D_, h_hi, h_lo);

        bf16x3_gemm<false><<<dim3(QKVW_ / 128, M_ / 128), 256, GEMM_SMEM_BYTES>>>(
            h_hi, h_lo, wqkvt_hi_i, wqkvt_lo_i, qkv, M_, QKVW_, D_);

        rope_kernel<<<(M_ * H_ * 32 + 255) / 256, 256>>>(qkv, H_, QKVW_, M_ * H_ * 32);
        rope_kernel<<<(M_ * HKV_ * 32 + 255) / 256, 256>>>(qkv + QW_, HKV_, QKVW_, M_ * HKV_ * 32);

        attn_kernel<<<dim3(B_ * H_, S_ / 8), 256>>>(qkv, att_hi, att_lo);

        bf16x3_gemm<true><<<dim3(D_ / 128, M_ / 128), 256, GEMM_SMEM_BYTES>>>(
            att_hi, att_lo, wot_hi_i, wot_lo_i, x, M_, D_, QW_);

        rmsnorm_split_kernel<<<M_, 256>>>(x, norm2_w + (size_t)i * D_, h_hi, h_lo);

        bf16x3_gemm<false><<<dim3(GUW_ / 128, M_ / 128), 256, GEMM_SMEM_BYTES>>>(
            h_hi, h_lo, wgut_hi_i, wgut_lo_i, gu, M_, GUW_, D_);

        silumul_split_kernel<<<(M_ * FF_ + 255) / 256, 256>>>(gu, gs_hi, gs_lo, M_ * FF_);

        bf16x3_gemm<true><<<dim3(D_ / 128, M_ / 128), 256, GEMM_SMEM_BYTES>>>(
            gs_hi, gs_lo, wdt_hi_i, wdt_lo_i, x, M_, D_, FF_);
    }

    rmsnorm_split_kernel<<<M_, 256>>>(x, final_norm, h_hi, h_lo);

    // logits = h @ embed^T ; embed is [V, D] = [N, K] row-major already
    bf16x3_gemm<false><<<dim3(V_ / 128, M_ / 128), 256, GEMM_SMEM_BYTES>>>(
        h_hi, h_lo, emb_hi, emb_lo, out, M_, V_, D_);
}

// round 13
// speedup vs baseline: 2.6409x; 1.1470x over previous
#include <cuda_runtime.h>
#include <cuda_bf16.h>
#include <math.h>
#include <stdint.h>

// Problem constants
#define V_   32000
#define D_   1024
#define H_   16
#define HKV_ 4
#define FF_  4096
#define L_   8
#define HD_  64
#define NREP_ 4
#define B_   2
#define S_   1024
#define M_   (B_*S_)      // 2048 tokens
#define KVW_ (HKV_*HD_)   // 256
#define QW_  (H_*HD_)     // 1024
#define QKVW_ (QW_ + 2*KVW_)   // 1536
#define GUW_  (2*FF_)          // 8192

// ---------------- scratch (device globals; no allocation allowed) ----------
__device__ float g_x   [M_*D_];
__device__ float g_qkv [M_*QKVW_];
__device__ float g_gu  [M_*GUW_];
// split (hi/lo bf16) activations
__device__ __align__(16) uint16_t g_h_hi  [M_*D_],  g_h_lo  [M_*D_];
__device__ __align__(16) uint16_t g_att_hi[M_*QW_], g_att_lo[M_*QW_];
__device__ __align__(16) uint16_t g_gs_hi [M_*FF_], g_gs_lo [M_*FF_];
// split transposed weights for ALL layers ([N,K] row-major per layer)
__device__ __align__(16) uint16_t g_wqkvt_hi[L_*QKVW_*D_], g_wqkvt_lo[L_*QKVW_*D_];
__device__ __align__(16) uint16_t g_wot_hi  [L_*D_*QW_],   g_wot_lo  [L_*D_*QW_];
__device__ __align__(16) uint16_t g_wgut_hi [L_*GUW_*D_],  g_wgut_lo [L_*GUW_*D_];
__device__ __align__(16) uint16_t g_wdt_hi  [L_*D_*FF_],   g_wdt_lo  [L_*D_*FF_];
// split embed table (for logits GEMM B operand)
__device__ __align__(16) uint16_t g_emb_hi[V_*D_], g_emb_lo[V_*D_];

// ---------------- helpers ---------------------------------------------------
__device__ __forceinline__ uint32_t smem_u32(const void* p) {
    uint32_t a;
    asm("{ .reg .u64 t; cvta.to.shared.u64 t, %1; cvt.u32.u64 %0, t; }"
        : "=r"(a) : "l"(p));
    return a;
}
__device__ __forceinline__ uint16_t bfbits(__nv_bfloat16 h) {
    return *reinterpret_cast<uint16_t*>(&h);
}
__device__ __forceinline__ void split_w(uint16_t* hi, uint16_t* lo, size_t idx, float v) {
    __nv_bfloat16 hb = __float2bfloat16_rn(v);
    float l = v - __bfloat162float(hb);
    __nv_bfloat16 lb = __float2bfloat16_rn(l);
    hi[idx] = bfbits(hb);
    lo[idx] = bfbits(lb);
}

#define CP_A16(s, g) asm volatile("cp.async.cg.shared.global [%0], [%1], 16;" :: "r"(s), "l"(g))
#define CP_COMMIT()  asm volatile("cp.async.commit_group;" ::: "memory")
#define CP_WAIT1()   asm volatile("cp.async.wait_group 1;" ::: "memory")
#define CP_WAIT0()   asm volatile("cp.async.wait_group 0;" ::: "memory")

__device__ __forceinline__ void ldm_x4(uint32_t a, uint32_t& r0, uint32_t& r1,
                                       uint32_t& r2, uint32_t& r3) {
    asm volatile("ldmatrix.sync.aligned.m8n8.x4.shared.b16 {%0,%1,%2,%3}, [%4];"
                 : "=r"(r0), "=r"(r1), "=r"(r2), "=r"(r3) : "r"(a));
}

__device__ __forceinline__ void mma_bf16_16x8x16(float* c, uint32_t a0, uint32_t a1,
                                                 uint32_t a2, uint32_t a3,
                                                 uint32_t b0, uint32_t b1) {
    asm volatile(
        "mma.sync.aligned.m16n8k16.row.col.f32.bf16.bf16.f32 "
        "{%0,%1,%2,%3}, {%4,%5,%6,%7}, {%8,%9}, {%0,%1,%2,%3};"
        : "+f"(c[0]), "+f"(c[1]), "+f"(c[2]), "+f"(c[3])
        : "r"(a0), "r"(a1), "r"(a2), "r"(a3), "r"(b0), "r"(b1));
}

// ================= bf16x3 split GEMM (NT), pre-split operands ==============
// C[M,N] = (ACC ? C : 0) + (Ahi+Alo)[M,K] * (Bhi+Blo)[N,K]^T  (drop lo*lo).
// CTA tile 128x128, BK=32, 256 threads (8 warps, warp tile 64x32).
// XOR-swizzled SMEM (64B pitch): off(row,chunk)=row*64+((chunk^((row>>1)&3))*16)
// -> conflict-free for cp.async stores AND ldmatrix reads, no padding waste.
// 3 stages x 32KB = 96KB -> 2 CTAs/SM. ONE __syncthreads per K-iter.
#define COMPB  (128 * 64)         // 8192 B per component
#define BUFB   (4 * COMPB)        // 32768 B per stage
#define NSTAGE 3
#define GEMM_SMEM_BYTES (NSTAGE * BUFB)   // 98304 B

__device__ __forceinline__ uint32_t swz(int row, int chunk) {
    return (uint32_t)(row * 64 + ((chunk ^ ((row >> 1) & 3)) << 4));
}

__device__ __forceinline__ void issue_tile(uint32_t sbuf,
    const uint16_t* Ahi, const uint16_t* Alo,
    const uint16_t* Bhi, const uint16_t* Blo,
    int brow, int bcol, int K, int k0, int tid)
{
#pragma unroll
    for (int c = 0; c < 2; c++) {
        int idx = tid + c * 256;
        int row = idx >> 2;
        int ch  = idx & 3;
        uint32_t so = swz(row, ch);
        size_t goA = (size_t)(brow + row) * K + k0 + ch * 8;
        size_t goB = (size_t)(bcol + row) * K + k0 + ch * 8;
        CP_A16(sbuf + so,             Ahi + goA);
        CP_A16(sbuf + COMPB + so,     Alo + goA);
        CP_A16(sbuf + 2 * COMPB + so, Bhi + goB);
        CP_A16(sbuf + 3 * COMPB + so, Blo + goB);
    }
    CP_COMMIT();
}

template <bool ACC>
__global__ __launch_bounds__(256, 2)
void bf16x3_gemm(const uint16_t* __restrict__ Ahi, const uint16_t* __restrict__ Alo,
                 const uint16_t* __restrict__ Bhi, const uint16_t* __restrict__ Blo,
                 float* __restrict__ C, int M, int N, int K) {
    extern __shared__ char smem[];
    const uint32_t sb = smem_u32(smem);
    const int tid    = threadIdx.x;
    const int wid    = tid >> 5;
    const int lane   = tid & 31;
    const int warp_m = (wid & 1) * 64;
    const int warp_n = (wid >> 1) * 32;
    const int brow   = blockIdx.y * 128;
    const int bcol   = blockIdx.x * 128;

    float acc[4][4][4];
#pragma unroll
    for (int i = 0; i < 4; i++)
#pragma unroll
        for (int j = 0; j < 4; j++)
#pragma unroll
            for (int r = 0; r < 4; r++) acc[i][j][r] = 0.f;

    const int niter = K >> 5;

    // prologue: stage 0,1
    issue_tile(sb,        Ahi, Alo, Bhi, Blo, brow, bcol, K, 0,  tid);
    issue_tile(sb + BUFB, Ahi, Alo, Bhi, Blo, brow, bcol, K, 32, tid);

    // ldmatrix lane address components
    const int a_r = lane & 15;                       // row within 16
    const int a_h = (lane >> 4) & 1;                 // k-half chunk
    const int b_r = ((lane >> 4) & 1) * 8 + (lane & 7);
    const int b_h = (lane >> 3) & 1;

    int s_cur = 0;
    int s_nxt = 2;
    for (int it = 0; it < niter; it++) {
        if (it + 1 < niter) CP_WAIT1(); else CP_WAIT0();
        __syncthreads();
        if (it + 2 < niter)
            issue_tile(sb + (uint32_t)s_nxt * BUFB, Ahi, Alo, Bhi, Blo,
                       brow, bcol, K, (it + 2) << 5, tid);

        const uint32_t buf = sb + (uint32_t)s_cur * BUFB;
        const uint32_t Ah = buf, Al = buf + COMPB, Bh = buf + 2 * COMPB, Bl = buf + 3 * COMPB;
#pragma unroll
        for (int ks = 0; ks < 2; ks++) {
            // B fragments for this k16 step (kept resident)
            uint32_t bhf[2][4], blf[2][4];
#pragma unroll
            for (int pr = 0; pr < 2; pr++) {
                int brow_l = warp_n + pr * 16 + b_r;
                uint32_t off = swz(brow_l, ks * 2 + b_h);
                ldm_x4(Bh + off, bhf[pr][0], bhf[pr][1], bhf[pr][2], bhf[pr][3]);
                ldm_x4(Bl + off, blf[pr][0], blf[pr][1], blf[pr][2], blf[pr][3]);
            }
#pragma unroll
            for (int mt = 0; mt < 4; mt++) {
                int arow = warp_m + mt * 16 + a_r;
                uint32_t off = swz(arow, ks * 2 + a_h);
                uint32_t ah0, ah1, ah2, ah3, al0, al1, al2, al3;
                ldm_x4(Ah + off, ah0, ah1, ah2, ah3);
                ldm_x4(Al + off, al0, al1, al2, al3);
                // pass 1: Ahi * Bhi (4 independent MMAs)
#pragma unroll
                for (int nt = 0; nt < 4; nt++) {
                    const int pr = nt >> 1, hf = (nt & 1) * 2;
                    mma_bf16_16x8x16(acc[mt][nt], ah0, ah1, ah2, ah3,
                                     bhf[pr][hf], bhf[pr][hf + 1]);
                }
                // pass 2: Ahi * Blo
#pragma unroll
                for (int nt = 0; nt < 4; nt++) {
                    const int pr = nt >> 1, hf = (nt & 1) * 2;
                    mma_bf16_16x8x16(acc[mt][nt], ah0, ah1, ah2, ah3,
                                     blf[pr][hf], blf[pr][hf + 1]);
                }
                // pass 3: Alo * Bhi
#pragma unroll
                for (int nt = 0; nt < 4; nt++) {
                    const int pr = nt >> 1, hf = (nt & 1) * 2;
                    mma_bf16_16x8x16(acc[mt][nt], al0, al1, al2, al3,
                                     bhf[pr][hf], bhf[pr][hf + 1]);
                }
            }
        }
        s_cur = (s_cur == NSTAGE - 1) ? 0 : s_cur + 1;
        s_nxt = (s_nxt == NSTAGE - 1) ? 0 : s_nxt + 1;
    }

    // epilogue (m16n8 C layout)
    const int g = lane >> 2, t = lane & 3;
#pragma unroll
    for (int mt = 0; mt < 4; mt++) {
        int r0 = brow + warp_m + mt * 16 + g;
#pragma unroll
        for (int nt = 0; nt < 4; nt++) {
            int c0 = bcol + warp_n + nt * 8 + t * 2;
            float2* p0 = (float2*)(C + (size_t)r0 * N + c0);
            float2* p1 = (float2*)(C + (size_t)(r0 + 8) * N + c0);
            float2 v0 = make_float2(acc[mt][nt][0], acc[mt][nt][1]);
            float2 v1 = make_float2(acc[mt][nt][2], acc[mt][nt][3]);
            if (ACC) {
                float2 o0 = *p0, o1 = *p1;
                v0.x += o0.x; v0.y += o0.y;
                v1.x += o1.x; v1.y += o1.y;
            }
            *p0 = v0;
            *p1 = v1;
        }
    }
}

// ----- batched weight transpose+split: [K,N] fp32 -> [N,K] bf16 hi/lo -------
__global__ void transpose_split_batched(const float* __restrict__ in,
                                        uint16_t* __restrict__ hi,
                                        uint16_t* __restrict__ lo,
                                        int K, int N,
                                        size_t in_lstride, size_t out_lstride) {
    __shared__ float tile[32][33];
    int z = blockIdx.z;
    in += (size_t)z * in_lstride;
    hi += (size_t)z * out_lstride;
    lo += (size_t)z * out_lstride;
    int kx = blockIdx.x * 32, ny = blockIdx.y * 32;
    int tx = threadIdx.x, ty = threadIdx.y;
#pragma unroll
    for (int r = ty; r < 32; r += 8)
        tile[r][tx] = in[(size_t)(kx + r) * N + ny + tx];
    __syncthreads();
#pragma unroll
    for (int r = ty; r < 32; r += 8)
        split_w(hi, lo, (size_t)(ny + r) * K + kx + tx, tile[tx][r]);
}

// ------------- elementwise split (embed table) ------------------------------
__global__ void split4_kernel(const float4* __restrict__ in,
                              uint2* __restrict__ hi, uint2* __restrict__ lo, int n4) {
    int i = blockIdx.x * blockDim.x + threadIdx.x;
    if (i >= n4) return;
    float4 v = in[i];
    __nv_bfloat16 h0 = __float2bfloat16_rn(v.x), h1 = __float2bfloat16_rn(v.y);
    __nv_bfloat16 h2 = __float2bfloat16_rn(v.z), h3 = __float2bfloat16_rn(v.w);
    __nv_bfloat16 l0 = __float2bfloat16_rn(v.x - __bfloat162float(h0));
    __nv_bfloat16 l1 = __float2bfloat16_rn(v.y - __bfloat162float(h1));
    __nv_bfloat16 l2 = __float2bfloat16_rn(v.z - __bfloat162float(h2));
    __nv_bfloat16 l3 = __float2bfloat16_rn(v.w - __bfloat162float(h3));
    hi[i] = make_uint2((uint32_t)bfbits(h0) | ((uint32_t)bfbits(h1) << 16),
                       (uint32_t)bfbits(h2) | ((uint32_t)bfbits(h3) << 16));
    lo[i] = make_uint2((uint32_t)bfbits(l0) | ((uint32_t)bfbits(l1) << 16),
                       (uint32_t)bfbits(l2) | ((uint32_t)bfbits(l3) << 16));
}

// ---------------- embedding gather ----------------------------------------
__global__ void embed_kernel(const int* __restrict__ tokens,
                             const float* __restrict__ embed,
                             float* __restrict__ x) {
    int m = blockIdx.x;
    int tkn = tokens[m];
    const float4* src = (const float4*)(embed + (size_t)tkn * D_);
    float4*       dst = (float4*)(x + (size_t)m * D_);
    for (int i = threadIdx.x; i < D_ / 4; i += blockDim.x) dst[i] = src[i];
}

// ---------------- RMSNorm -> split bf16 output ------------------------------
__global__ void rmsnorm_split_kernel(const float* __restrict__ x,
                                     const float* __restrict__ w,
                                     uint16_t* __restrict__ hi,
                                     uint16_t* __restrict__ lo) {
    int m = blockIdx.x;
    const float* xr = x + (size_t)m * D_;
    float ss = 0.f;
    for (int i = threadIdx.x; i < D_; i += 256) { float v = xr[i]; ss += v * v; }
    ss += __shfl_xor_sync(0xffffffffu, ss, 16);
    ss += __shfl_xor_sync(0xffffffffu, ss, 8);
    ss += __shfl_xor_sync(0xffffffffu, ss, 4);
    ss += __shfl_xor_sync(0xffffffffu, ss, 2);
    ss += __shfl_xor_sync(0xffffffffu, ss, 1);
    __shared__ float red[8];
    int wid = threadIdx.x >> 5, lane = threadIdx.x & 31;
    if (lane == 0) red[wid] = ss;
    __syncthreads();
    float tot = red[0] + red[1] + red[2] + red[3] + red[4] + red[5] + red[6] + red[7];
    float rn = rsqrtf(tot / (float)D_ + 1e-6f);
    for (int i = threadIdx.x; i < D_; i += 256)
        split_w(hi, lo, (size_t)m * D_ + i, xr[i] * rn * w[i]);
}

// ---------------- RoPE (in place, pairs (i, i+32) per thread) ---------------
__global__ void rope_kernel(float* __restrict__ x, int nheads, int rowstride, int total) {
    int idx = blockIdx.x * blockDim.x + threadIdx.x;
    if (idx >= total) return;
    int i    = idx & 31;
    int head = (idx >> 5) % nheads;
    int m    = idx / (32 * nheads);
    int s    = m % S_;
    float inv_freq = expf(-(float)(2 * i) * (1.0f / 64.0f) * 9.210340371976184f);
    float ang = (float)s * inv_freq;
    float sn, cs;
    sincosf(ang, &sn, &cs);
    float* base = x + (size_t)m * rowstride + head * HD_;
    float x1 = base[i];
    float x2 = base[i + 32];
    base[i]      = x1 * cs - x2 * sn;
    base[i + 32] = x2 * cs + x1 * sn;
}

// -------- causal attention (warp per query row), reads fused qkv ------------
__global__ void attn_kernel(const float* __restrict__ qkv,
                            uint16_t* __restrict__ out_hi,
                            uint16_t* __restrict__ out_lo) {
    int bh   = blockIdx.x;
    int b    = bh / H_;
    int h    = bh % H_;
    int gq   = h / NREP_;
    int warp = threadIdx.x >> 5;
    int lane = threadIdx.x & 31;
    int s    = blockIdx.y * 8 + warp;

    const float2* qp = (const float2*)(qkv + (size_t)(b * S_ + s) * QKVW_ + h * HD_);
    float2 qv = qp[lane];
    const float* kbase = qkv + (size_t)b * S_ * QKVW_ + QW_ + gq * HD_;
    const float* vbase = qkv + (size_t)b * S_ * QKVW_ + QW_ + KVW_ + gq * HD_;

    float mx = -INFINITY, l = 0.f, a0 = 0.f, a1 = 0.f;
    const float inv_scale = 0.125f;

    for (int j = 0; j <= s; j++) {
        float2 kv2 = *(const float2*)(kbase + (size_t)j * QKVW_ + lane * 2);
        float p = qv.x * kv2.x + qv.y * kv2.y;
        p += __shfl_xor_sync(0xffffffffu, p, 16);
        p += __shfl_xor_sync(0xffffffffu, p, 8);
        p += __shfl_xor_sync(0xffffffffu, p, 4);
        p += __shfl_xor_sync(0xffffffffu, p, 2);
        p += __shfl_xor_sync(0xffffffffu, p, 1);
        float sc = p * inv_scale;
        float mn = fmaxf(mx, sc);
        float corr = __expf(mx - mn);
        float pe   = __expf(sc - mn);
        l = l * corr + pe;
        float2 vv = *(const float2*)(vbase + (size_t)j * QKVW_ + lane * 2);
        a0 = a0 * corr + pe * vv.x;
        a1 = a1 * corr + pe * vv.y;
        mx = mn;
    }
    float invl = 1.f / l;
    size_t base_idx = (size_t)(b * S_ + s) * QW_ + h * HD_ + lane * 2;
    split_w(out_hi, out_lo, base_idx,     a0 * invl);
    split_w(out_hi, out_lo, base_idx + 1, a1 * invl);
}

// ------- SiLU(gate)*up from fused gu buffer -> split bf16 -------------------
__global__ void silumul_split_kernel(const float* __restrict__ gu,
                                     uint16_t* __restrict__ hi,
                                     uint16_t* __restrict__ lo, int n) {
    int idx = blockIdx.x * blockDim.x + threadIdx.x;
    if (idx >= n) return;
    int m = idx >> 12;          // / FF_
    int j = idx & (FF_ - 1);
    float gv = gu[(size_t)m * GUW_ + j];
    float uv = gu[(size_t)m * GUW_ + FF_ + j];
    float sig = 1.f / (1.f + __expf(-gv));
    split_w(hi, lo, idx, gv * sig * uv);
}

// ---------------- driver ----------------------------------------------------
extern "C" void kernel_launch(void* const* d_in, const int* in_sizes, int n_in,
                              void* d_out, int out_size) {
    const int*   tokens     = (const int*)d_in[0];
    const float* embed      = (const float*)d_in[1];
    const float* wq         = (const float*)d_in[2];
    const float* wk         = (const float*)d_in[3];
    const float* wv         = (const float*)d_in[4];
    const float* wo         = (const float*)d_in[5];
    const float* w_gate     = (const float*)d_in[6];
    const float* w_up       = (const float*)d_in[7];
    const float* w_down     = (const float*)d_in[8];
    const float* norm1_w    = (const float*)d_in[9];
    const float* norm2_w    = (const float*)d_in[10];
    const float* final_norm = (const float*)d_in[11];
    float* out = (float*)d_out;

    float *x, *qkv, *gu;
    uint16_t *h_hi, *h_lo, *att_hi, *att_lo, *gs_hi, *gs_lo;
    uint16_t *wqkvt_hi, *wqkvt_lo, *wot_hi, *wot_lo, *wgut_hi, *wgut_lo, *wdt_hi, *wdt_lo;
    uint16_t *emb_hi, *emb_lo;
    cudaGetSymbolAddress((void**)&x,    g_x);
    cudaGetSymbolAddress((void**)&qkv,  g_qkv);
    cudaGetSymbolAddress((void**)&gu,   g_gu);
    cudaGetSymbolAddress((void**)&h_hi,   g_h_hi);
    cudaGetSymbolAddress((void**)&h_lo,   g_h_lo);
    cudaGetSymbolAddress((void**)&att_hi, g_att_hi);
    cudaGetSymbolAddress((void**)&att_lo, g_att_lo);
    cudaGetSymbolAddress((void**)&gs_hi,  g_gs_hi);
    cudaGetSymbolAddress((void**)&gs_lo,  g_gs_lo);
    cudaGetSymbolAddress((void**)&wqkvt_hi, g_wqkvt_hi);
    cudaGetSymbolAddress((void**)&wqkvt_lo, g_wqkvt_lo);
    cudaGetSymbolAddress((void**)&wot_hi,   g_wot_hi);
    cudaGetSymbolAddress((void**)&wot_lo,   g_wot_lo);
    cudaGetSymbolAddress((void**)&wgut_hi,  g_wgut_hi);
    cudaGetSymbolAddress((void**)&wgut_lo,  g_wgut_lo);
    cudaGetSymbolAddress((void**)&wdt_hi,   g_wdt_hi);
    cudaGetSymbolAddress((void**)&wdt_lo,   g_wdt_lo);
    cudaGetSymbolAddress((void**)&emb_hi,   g_emb_hi);
    cudaGetSymbolAddress((void**)&emb_lo,   g_emb_lo);

    cudaFuncSetAttribute(bf16x3_gemm<false>,
                         cudaFuncAttributeMaxDynamicSharedMemorySize, GEMM_SMEM_BYTES);
    cudaFuncSetAttribute(bf16x3_gemm<true>,
                         cudaFuncAttributeMaxDynamicSharedMemorySize, GEMM_SMEM_BYTES);

    embed_kernel<<<M_, 256>>>(tokens, embed, x);
    split4_kernel<<<(V_ * D_ / 4 + 255) / 256, 256>>>((const float4*)embed,
                                                      (uint2*)emb_hi, (uint2*)emb_lo,
                                                      V_ * D_ / 4);

    // ---- batched transposes for all layers (7 launches total) ----
    dim3 t32(32, 8);
    const size_t QKV_L = (size_t)QKVW_ * D_;
    const size_t GU_L  = (size_t)GUW_ * D_;
    transpose_split_batched<<<dim3(D_ / 32, QW_ / 32, L_), t32>>>(
        wq, wqkvt_hi, wqkvt_lo, D_, QW_, (size_t)D_ * QW_, QKV_L);
    transpose_split_batched<<<dim3(D_ / 32, KVW_ / 32, L_), t32>>>(
        wk, wqkvt_hi + (size_t)QW_ * D_, wqkvt_lo + (size_t)QW_ * D_,
        D_, KVW_, (size_t)D_ * KVW_, QKV_L);
    transpose_split_batched<<<dim3(D_ / 32, KVW_ / 32, L_), t32>>>(
        wv, wqkvt_hi + (size_t)(QW_ + KVW_) * D_, wqkvt_lo + (size_t)(QW_ + KVW_) * D_,
        D_, KVW_, (size_t)D_ * KVW_, QKV_L);
    transpose_split_batched<<<dim3(QW_ / 32, D_ / 32, L_), t32>>>(
        wo, wot_hi, wot_lo, QW_, D_, (size_t)QW_ * D_, (size_t)D_ * QW_);
    transpose_split_batched<<<dim3(D_ / 32, FF_ / 32, L_), t32>>>(
        w_gate, wgut_hi, wgut_lo, D_, FF_, (size_t)D_ * FF_, GU_L);
    transpose_split_batched<<<dim3(D_ / 32, FF_ / 32, L_), t32>>>(
        w_up, wgut_hi + (size_t)FF_ * D_, wgut_lo + (size_t)FF_ * D_,
        D_, FF_, (size_t)D_ * FF_, GU_L);
    transpose_split_batched<<<dim3(FF_ / 32, D_ / 32, L_), t32>>>(
        w_down, wdt_hi, wdt_lo, FF_, D_, (size_t)FF_ * D_, (size_t)D_ * FF_);

    for (int i = 0; i < L_; i++) {
        const uint16_t* wqkvt_hi_i = wqkvt_hi + (size_t)i * QKV_L;
        const uint16_t* wqkvt_lo_i = wqkvt_lo + (size_t)i * QKV_L;
        const uint16_t* wot_hi_i   = wot_hi + (size_t)i * D_ * QW_;
        const uint16_t* wot_lo_i   = wot_lo + (size_t)i * D_ * QW_;
        const uint16_t* wgut_hi_i  = wgut_hi + (size_t)i * GU_L;
        const uint16_t* wgut_lo_i  = wgut_lo + (size_t)i * GU_L;
        const uint16_t* wdt_hi_i   = wdt_hi + (size_t)i * D_ * FF_;
        const uint16_t* wdt_lo_i   = wdt_lo + (size_t)i * D_ * FF_;

        rmsnorm_split_kernel<<<M_, 256>>>(x, norm1_w + (size_t)i * D_, h_hi, h_lo);

        bf16x3_gemm<false><<<dim3(QKVW_ / 128, M_ / 128), 256, GEMM_SMEM_BYTES>>>(
            h_hi, h_lo, wqkvt_hi_i, wqkvt_lo_i, qkv, M_, QKVW_, D_);

        rope_kernel<<<(M_ * H_ * 32 + 255) / 256, 256>>>(qkv, H_, QKVW_, M_ * H_ * 32);
        rope_kernel<<<(M_ * HKV_ * 32 + 255) / 256, 256>>>(qkv + QW_, HKV_, QKVW_, M_ * HKV_ * 32);

        attn_kernel<<<dim3(B_ * H_, S_ / 8), 256>>>(qkv, att_hi, att_lo);

        bf16x3_gemm<true><<<dim3(D_ / 128, M_ / 128), 256, GEMM_SMEM_BYTES>>>(
            att_hi, att_lo, wot_hi_i, wot_lo_i, x, M_, D_, QW_);

        rmsnorm_split_kernel<<<M_, 256>>>(x, norm2_w + (size_t)i * D_, h_hi, h_lo);

        bf16x3_gemm<false><<<dim3(GUW_ / 128, M_ / 128), 256, GEMM_SMEM_BYTES>>>(
            h_hi, h_lo, wgut_hi_i, wgut_lo_i, gu, M_, GUW_, D_);

        silumul_split_kernel<<<(M_ * FF_ + 255) / 256, 256>>>(gu, gs_hi, gs_lo, M_ * FF_);

        bf16x3_gemm<true><<<dim3(D_ / 128, M_ / 128), 256, GEMM_SMEM_BYTES>>>(
            gs_hi, gs_lo, wdt_hi_i, wdt_lo_i, x, M_, D_, FF_);
    }

    rmsnorm_split_kernel<<<M_, 256>>>(x, final_norm, h_hi, h_lo);

    // logits = h @ embed^T ; embed is [V, D] = [N, K] row-major already
    bf16x3_gemm<false><<<dim3(V_ / 128, M_ / 128), 256, GEMM_SMEM_BYTES>>>(
        h_hi, h_lo, emb_hi, emb_lo, out, M_, V_, D_);
}

// round 14
// speedup vs baseline: 3.2082x; 1.2148x over previous
#include <cuda_runtime.h>
#include <cuda_bf16.h>
#include <math.h>
#include <stdint.h>

// Problem constants
#define V_   32000
#define D_   1024
#define H_   16
#define HKV_ 4
#define FF_  4096
#define L_   8
#define HD_  64
#define NREP_ 4
#define B_   2
#define S_   1024
#define M_   (B_*S_)      // 2048 tokens
#define KVW_ (HKV_*HD_)   // 256
#define QW_  (H_*HD_)     // 1024
#define QKVW_ (QW_ + 2*KVW_)   // 1536
#define GUW_  (2*FF_)          // 8192

// ---------------- scratch (device globals; no allocation allowed) ----------
__device__ float g_x   [M_*D_];
__device__ float g_qkv [M_*QKVW_];
__device__ float g_gu  [M_*GUW_];
// split (hi/lo bf16) activations
__device__ __align__(16) uint16_t g_h_hi  [M_*D_],  g_h_lo  [M_*D_];
__device__ __align__(16) uint16_t g_att_hi[M_*QW_], g_att_lo[M_*QW_];
__device__ __align__(16) uint16_t g_gs_hi [M_*FF_], g_gs_lo [M_*FF_];
// split transposed weights for ALL layers ([N,K] row-major per layer)
__device__ __align__(16) uint16_t g_wqkvt_hi[L_*QKVW_*D_], g_wqkvt_lo[L_*QKVW_*D_];
__device__ __align__(16) uint16_t g_wot_hi  [L_*D_*QW_],   g_wot_lo  [L_*D_*QW_];
__device__ __align__(16) uint16_t g_wgut_hi [L_*GUW_*D_],  g_wgut_lo [L_*GUW_*D_];
__device__ __align__(16) uint16_t g_wdt_hi  [L_*D_*FF_],   g_wdt_lo  [L_*D_*FF_];
// split embed table (for logits GEMM B operand)
__device__ __align__(16) uint16_t g_emb_hi[V_*D_], g_emb_lo[V_*D_];

// ---------------- helpers ---------------------------------------------------
__device__ __forceinline__ uint32_t smem_u32(const void* p) {
    uint32_t a;
    asm("{ .reg .u64 t; cvta.to.shared.u64 t, %1; cvt.u32.u64 %0, t; }"
        : "=r"(a) : "l"(p));
    return a;
}
__device__ __forceinline__ uint16_t bfbits(__nv_bfloat16 h) {
    return *reinterpret_cast<uint16_t*>(&h);
}
__device__ __forceinline__ void split_w(uint16_t* hi, uint16_t* lo, size_t idx, float v) {
    __nv_bfloat16 hb = __float2bfloat16_rn(v);
    float l = v - __bfloat162float(hb);
    __nv_bfloat16 lb = __float2bfloat16_rn(l);
    hi[idx] = bfbits(hb);
    lo[idx] = bfbits(lb);
}

#define CP_A16(s, g) asm volatile("cp.async.cg.shared.global [%0], [%1], 16;" :: "r"(s), "l"(g))
#define CP_COMMIT()  asm volatile("cp.async.commit_group;" ::: "memory")
#define CP_WAIT1()   asm volatile("cp.async.wait_group 1;" ::: "memory")
#define CP_WAIT0()   asm volatile("cp.async.wait_group 0;" ::: "memory")

__device__ __forceinline__ void ldm_x4(uint32_t a, uint32_t& r0, uint32_t& r1,
                                       uint32_t& r2, uint32_t& r3) {
    asm volatile("ldmatrix.sync.aligned.m8n8.x4.shared.b16 {%0,%1,%2,%3}, [%4];"
                 : "=r"(r0), "=r"(r1), "=r"(r2), "=r"(r3) : "r"(a));
}

__device__ __forceinline__ void mma_bf16_16x8x16(float* c, uint32_t a0, uint32_t a1,
                                                 uint32_t a2, uint32_t a3,
                                                 uint32_t b0, uint32_t b1) {
    asm volatile(
        "mma.sync.aligned.m16n8k16.row.col.f32.bf16.bf16.f32 "
        "{%0,%1,%2,%3}, {%4,%5,%6,%7}, {%8,%9}, {%0,%1,%2,%3};"
        : "+f"(c[0]), "+f"(c[1]), "+f"(c[2]), "+f"(c[3])
        : "r"(a0), "r"(a1), "r"(a2), "r"(a3), "r"(b0), "r"(b1));
}

// ================= bf16x3 split GEMM (NT), pre-split operands ==============
// (unchanged from R13 — 2 CTA/SM swizzled pipeline)
#define COMPB  (128 * 64)         // 8192 B per component
#define BUFB   (4 * COMPB)        // 32768 B per stage
#define NSTAGE 3
#define GEMM_SMEM_BYTES (NSTAGE * BUFB)   // 98304 B

__device__ __forceinline__ uint32_t swz(int row, int chunk) {
    return (uint32_t)(row * 64 + ((chunk ^ ((row >> 1) & 3)) << 4));
}

__device__ __forceinline__ void issue_tile(uint32_t sbuf,
    const uint16_t* Ahi, const uint16_t* Alo,
    const uint16_t* Bhi, const uint16_t* Blo,
    int brow, int bcol, int K, int k0, int tid)
{
#pragma unroll
    for (int c = 0; c < 2; c++) {
        int idx = tid + c * 256;
        int row = idx >> 2;
        int ch  = idx & 3;
        uint32_t so = swz(row, ch);
        size_t goA = (size_t)(brow + row) * K + k0 + ch * 8;
        size_t goB = (size_t)(bcol + row) * K + k0 + ch * 8;
        CP_A16(sbuf + so,             Ahi + goA);
        CP_A16(sbuf + COMPB + so,     Alo + goA);
        CP_A16(sbuf + 2 * COMPB + so, Bhi + goB);
        CP_A16(sbuf + 3 * COMPB + so, Blo + goB);
    }
    CP_COMMIT();
}

template <bool ACC>
__global__ __launch_bounds__(256, 2)
void bf16x3_gemm(const uint16_t* __restrict__ Ahi, const uint16_t* __restrict__ Alo,
                 const uint16_t* __restrict__ Bhi, const uint16_t* __restrict__ Blo,
                 float* __restrict__ C, int M, int N, int K) {
    extern __shared__ char smem[];
    const uint32_t sb = smem_u32(smem);
    const int tid    = threadIdx.x;
    const int wid    = tid >> 5;
    const int lane   = tid & 31;
    const int warp_m = (wid & 1) * 64;
    const int warp_n = (wid >> 1) * 32;
    const int brow   = blockIdx.y * 128;
    const int bcol   = blockIdx.x * 128;

    float acc[4][4][4];
#pragma unroll
    for (int i = 0; i < 4; i++)
#pragma unroll
        for (int j = 0; j < 4; j++)
#pragma unroll
            for (int r = 0; r < 4; r++) acc[i][j][r] = 0.f;

    const int niter = K >> 5;

    issue_tile(sb,        Ahi, Alo, Bhi, Blo, brow, bcol, K, 0,  tid);
    issue_tile(sb + BUFB, Ahi, Alo, Bhi, Blo, brow, bcol, K, 32, tid);

    const int a_r = lane & 15;
    const int a_h = (lane >> 4) & 1;
    const int b_r = ((lane >> 4) & 1) * 8 + (lane & 7);
    const int b_h = (lane >> 3) & 1;

    int s_cur = 0;
    int s_nxt = 2;
    for (int it = 0; it < niter; it++) {
        if (it + 1 < niter) CP_WAIT1(); else CP_WAIT0();
        __syncthreads();
        if (it + 2 < niter)
            issue_tile(sb + (uint32_t)s_nxt * BUFB, Ahi, Alo, Bhi, Blo,
                       brow, bcol, K, (it + 2) << 5, tid);

        const uint32_t buf = sb + (uint32_t)s_cur * BUFB;
        const uint32_t Ah = buf, Al = buf + COMPB, Bh = buf + 2 * COMPB, Bl = buf + 3 * COMPB;
#pragma unroll
        for (int ks = 0; ks < 2; ks++) {
            uint32_t bhf[2][4], blf[2][4];
#pragma unroll
            for (int pr = 0; pr < 2; pr++) {
                int brow_l = warp_n + pr * 16 + b_r;
                uint32_t off = swz(brow_l, ks * 2 + b_h);
                ldm_x4(Bh + off, bhf[pr][0], bhf[pr][1], bhf[pr][2], bhf[pr][3]);
                ldm_x4(Bl + off, blf[pr][0], blf[pr][1], blf[pr][2], blf[pr][3]);
            }
#pragma unroll
            for (int mt = 0; mt < 4; mt++) {
                int arow = warp_m + mt * 16 + a_r;
                uint32_t off = swz(arow, ks * 2 + a_h);
                uint32_t ah0, ah1, ah2, ah3, al0, al1, al2, al3;
                ldm_x4(Ah + off, ah0, ah1, ah2, ah3);
                ldm_x4(Al + off, al0, al1, al2, al3);
#pragma unroll
                for (int nt = 0; nt < 4; nt++) {
                    const int pr = nt >> 1, hf = (nt & 1) * 2;
                    mma_bf16_16x8x16(acc[mt][nt], ah0, ah1, ah2, ah3,
                                     bhf[pr][hf], bhf[pr][hf + 1]);
                }
#pragma unroll
                for (int nt = 0; nt < 4; nt++) {
                    const int pr = nt >> 1, hf = (nt & 1) * 2;
                    mma_bf16_16x8x16(acc[mt][nt], ah0, ah1, ah2, ah3,
                                     blf[pr][hf], blf[pr][hf + 1]);
                }
#pragma unroll
                for (int nt = 0; nt < 4; nt++) {
                    const int pr = nt >> 1, hf = (nt & 1) * 2;
                    mma_bf16_16x8x16(acc[mt][nt], al0, al1, al2, al3,
                                     bhf[pr][hf], bhf[pr][hf + 1]);
                }
            }
        }
        s_cur = (s_cur == NSTAGE - 1) ? 0 : s_cur + 1;
        s_nxt = (s_nxt == NSTAGE - 1) ? 0 : s_nxt + 1;
    }

    const int g = lane >> 2, t = lane & 3;
#pragma unroll
    for (int mt = 0; mt < 4; mt++) {
        int r0 = brow + warp_m + mt * 16 + g;
#pragma unroll
        for (int nt = 0; nt < 4; nt++) {
            int c0 = bcol + warp_n + nt * 8 + t * 2;
            float2* p0 = (float2*)(C + (size_t)r0 * N + c0);
            float2* p1 = (float2*)(C + (size_t)(r0 + 8) * N + c0);
            float2 v0 = make_float2(acc[mt][nt][0], acc[mt][nt][1]);
            float2 v1 = make_float2(acc[mt][nt][2], acc[mt][nt][3]);
            if (ACC) {
                float2 o0 = *p0, o1 = *p1;
                v0.x += o0.x; v0.y += o0.y;
                v1.x += o1.x; v1.y += o1.y;
            }
            *p0 = v0;
            *p1 = v1;
        }
    }
}

// ----- batched weight transpose+split: [K,N] fp32 -> [N,K] bf16 hi/lo -------
__global__ void transpose_split_batched(const float* __restrict__ in,
                                        uint16_t* __restrict__ hi,
                                        uint16_t* __restrict__ lo,
                                        int K, int N,
                                        size_t in_lstride, size_t out_lstride) {
    __shared__ float tile[32][33];
    int z = blockIdx.z;
    in += (size_t)z * in_lstride;
    hi += (size_t)z * out_lstride;
    lo += (size_t)z * out_lstride;
    int kx = blockIdx.x * 32, ny = blockIdx.y * 32;
    int tx = threadIdx.x, ty = threadIdx.y;
#pragma unroll
    for (int r = ty; r < 32; r += 8)
        tile[r][tx] = in[(size_t)(kx + r) * N + ny + tx];
    __syncthreads();
#pragma unroll
    for (int r = ty; r < 32; r += 8)
        split_w(hi, lo, (size_t)(ny + r) * K + kx + tx, tile[tx][r]);
}

// ------------- elementwise split (embed table) ------------------------------
__global__ void split4_kernel(const float4* __restrict__ in,
                              uint2* __restrict__ hi, uint2* __restrict__ lo, int n4) {
    int i = blockIdx.x * blockDim.x + threadIdx.x;
    if (i >= n4) return;
    float4 v = in[i];
    __nv_bfloat16 h0 = __float2bfloat16_rn(v.x), h1 = __float2bfloat16_rn(v.y);
    __nv_bfloat16 h2 = __float2bfloat16_rn(v.z), h3 = __float2bfloat16_rn(v.w);
    __nv_bfloat16 l0 = __float2bfloat16_rn(v.x - __bfloat162float(h0));
    __nv_bfloat16 l1 = __float2bfloat16_rn(v.y - __bfloat162float(h1));
    __nv_bfloat16 l2 = __float2bfloat16_rn(v.z - __bfloat162float(h2));
    __nv_bfloat16 l3 = __float2bfloat16_rn(v.w - __bfloat162float(h3));
    hi[i] = make_uint2((uint32_t)bfbits(h0) | ((uint32_t)bfbits(h1) << 16),
                       (uint32_t)bfbits(h2) | ((uint32_t)bfbits(h3) << 16));
    lo[i] = make_uint2((uint32_t)bfbits(l0) | ((uint32_t)bfbits(l1) << 16),
                       (uint32_t)bfbits(l2) | ((uint32_t)bfbits(l3) << 16));
}

// ---------------- embedding gather ----------------------------------------
__global__ void embed_kernel(const int* __restrict__ tokens,
                             const float* __restrict__ embed,
                             float* __restrict__ x) {
    int m = blockIdx.x;
    int tkn = tokens[m];
    const float4* src = (const float4*)(embed + (size_t)tkn * D_);
    float4*       dst = (float4*)(x + (size_t)m * D_);
    for (int i = threadIdx.x; i < D_ / 4; i += blockDim.x) dst[i] = src[i];
}

// ---------------- RMSNorm -> split bf16 output ------------------------------
__global__ void rmsnorm_split_kernel(const float* __restrict__ x,
                                     const float* __restrict__ w,
                                     uint16_t* __restrict__ hi,
                                     uint16_t* __restrict__ lo) {
    int m = blockIdx.x;
    const float* xr = x + (size_t)m * D_;
    float ss = 0.f;
    for (int i = threadIdx.x; i < D_; i += 256) { float v = xr[i]; ss += v * v; }
    ss += __shfl_xor_sync(0xffffffffu, ss, 16);
    ss += __shfl_xor_sync(0xffffffffu, ss, 8);
    ss += __shfl_xor_sync(0xffffffffu, ss, 4);
    ss += __shfl_xor_sync(0xffffffffu, ss, 2);
    ss += __shfl_xor_sync(0xffffffffu, ss, 1);
    __shared__ float red[8];
    int wid = threadIdx.x >> 5, lane = threadIdx.x & 31;
    if (lane == 0) red[wid] = ss;
    __syncthreads();
    float tot = red[0] + red[1] + red[2] + red[3] + red[4] + red[5] + red[6] + red[7];
    float rn = rsqrtf(tot / (float)D_ + 1e-6f);
    for (int i = threadIdx.x; i < D_; i += 256)
        split_w(hi, lo, (size_t)m * D_ + i, xr[i] * rn * w[i]);
}

// ---------------- RoPE (in place, pairs (i, i+32) per thread) ---------------
__global__ void rope_kernel(float* __restrict__ x, int nheads, int rowstride, int total) {
    int idx = blockIdx.x * blockDim.x + threadIdx.x;
    if (idx >= total) return;
    int i    = idx & 31;
    int head = (idx >> 5) % nheads;
    int m    = idx / (32 * nheads);
    int s    = m % S_;
    float inv_freq = expf(-(float)(2 * i) * (1.0f / 64.0f) * 9.210340371976184f);
    float ang = (float)s * inv_freq;
    float sn, cs;
    sincosf(ang, &sn, &cs);
    float* base = x + (size_t)m * rowstride + head * HD_;
    float x1 = base[i];
    float x2 = base[i + 32];
    base[i]      = x1 * cs - x2 * sn;
    base[i + 32] = x2 * cs + x1 * sn;
}

// -------- tile-parallel causal attention ------------------------------------
// block = (b, g) x 2 query rows; 8 warps = 4 heads x 2 s. Shared K/V tile
// (32 keys x 64d, pad-68 rows) reused by all 8 warps. Phase 1: lane-per-key
// serial dot from smem; ONE shfl-butterfly per 32-key tile. Phase 2:
// d-parallel P*V accumulation with dual accumulators.
#define AT_TK 32
__global__ __launch_bounds__(256)
void attn_kernel(const float* __restrict__ qkv,
                 uint16_t* __restrict__ out_hi,
                 uint16_t* __restrict__ out_lo) {
    __shared__ float Ks[AT_TK][68];
    __shared__ float Vs[AT_TK][68];
    __shared__ float Qs[8][64];
    __shared__ float Ps[8][AT_TK];

    const int bg   = blockIdx.x;
    const int b    = bg / HKV_;
    const int g    = bg % HKV_;
    const int wid  = threadIdx.x >> 5;
    const int lane = threadIdx.x & 31;
    const int head = g * NREP_ + (wid >> 1);
    const int s    = blockIdx.y * 2 + (wid & 1);
    const int smax = blockIdx.y * 2 + 1;

    // load q for this warp's (head, s) into smem
    {
        const float2* qp = (const float2*)(qkv + (size_t)(b * S_ + s) * QKVW_ + head * HD_);
        float2 qv = qp[lane];
        Qs[wid][2 * lane]     = qv.x;
        Qs[wid][2 * lane + 1] = qv.y;
    }

    const float* kbase = qkv + (size_t)b * S_ * QKVW_ + QW_ + g * HD_;
    const float* vbase = kbase + KVW_;

    float m = -INFINITY, l = 0.f;
    float o0a = 0.f, o1a = 0.f, o0b = 0.f, o1b = 0.f;
    const int ntiles = (smax + AT_TK) / AT_TK;

    for (int t = 0; t < ntiles; t++) {
        const int j0 = t * AT_TK;
        __syncthreads();   // previous tile fully consumed
        // cooperative K/V tile load: 512 float4 units over 256 threads
#pragma unroll
        for (int c = 0; c < 2; c++) {
            int u   = threadIdx.x + c * 256;
            int key = u >> 4, d4 = u & 15;
            int j   = j0 + key;
            float4 kk = make_float4(0.f, 0.f, 0.f, 0.f), vv = kk;
            if (j < S_) {
                kk = *(const float4*)(kbase + (size_t)j * QKVW_ + d4 * 4);
                vv = *(const float4*)(vbase + (size_t)j * QKVW_ + d4 * 4);
            }
            *(float4*)&Ks[key][d4 * 4] = kk;
            *(float4*)&Vs[key][d4 * 4] = vv;
        }
        __syncthreads();

        // phase 1: score for key j0+lane
        const int j = j0 + lane;
        float sc = -INFINITY;
        if (j <= s) {
            float acc0 = 0.f, acc1 = 0.f;
#pragma unroll
            for (int d4 = 0; d4 < 16; d4 += 2) {
                float4 k0 = *(const float4*)&Ks[lane][d4 * 4];
                float4 q0 = *(const float4*)&Qs[wid][d4 * 4];
                acc0 += k0.x * q0.x + k0.y * q0.y + k0.z * q0.z + k0.w * q0.w;
                float4 k1 = *(const float4*)&Ks[lane][d4 * 4 + 4];
                float4 q1 = *(const float4*)&Qs[wid][d4 * 4 + 4];
                acc1 += k1.x * q1.x + k1.y * q1.y + k1.z * q1.z + k1.w * q1.w;
            }
            sc = (acc0 + acc1) * 0.125f;
        }
        // tile max (one butterfly per 32 keys)
        float tm = sc;
        tm = fmaxf(tm, __shfl_xor_sync(0xffffffffu, tm, 16));
        tm = fmaxf(tm, __shfl_xor_sync(0xffffffffu, tm, 8));
        tm = fmaxf(tm, __shfl_xor_sync(0xffffffffu, tm, 4));
        tm = fmaxf(tm, __shfl_xor_sync(0xffffffffu, tm, 2));
        tm = fmaxf(tm, __shfl_xor_sync(0xffffffffu, tm, 1));
        float mn   = fmaxf(m, tm);
        float corr = __expf(m - mn);
        float p    = (j <= s) ? __expf(sc - mn) : 0.f;
        float ps = p;
        ps += __shfl_xor_sync(0xffffffffu, ps, 16);
        ps += __shfl_xor_sync(0xffffffffu, ps, 8);
        ps += __shfl_xor_sync(0xffffffffu, ps, 4);
        ps += __shfl_xor_sync(0xffffffffu, ps, 2);
        ps += __shfl_xor_sync(0xffffffffu, ps, 1);
        l = l * corr + ps;
        o0a *= corr; o1a *= corr; o0b *= corr; o1b *= corr;
        m = mn;

        Ps[wid][lane] = p;
        __syncwarp();
        // phase 2: d-parallel P*V (dual accumulators break the FMA chain)
#pragma unroll
        for (int jj = 0; jj < AT_TK; jj += 2) {
            float p0 = Ps[wid][jj];
            float p1 = Ps[wid][jj + 1];
            o0a += p0 * Vs[jj][2 * lane];
            o1a += p0 * Vs[jj][2 * lane + 1];
            o0b += p1 * Vs[jj + 1][2 * lane];
            o1b += p1 * Vs[jj + 1][2 * lane + 1];
        }
        __syncwarp();
    }

    float invl = 1.f / l;
    size_t base_idx = (size_t)(b * S_ + s) * QW_ + head * HD_ + lane * 2;
    split_w(out_hi, out_lo, base_idx,     (o0a + o0b) * invl);
    split_w(out_hi, out_lo, base_idx + 1, (o1a + o1b) * invl);
}

// ------- SiLU(gate)*up from fused gu buffer -> split bf16 -------------------
__global__ void silumul_split_kernel(const float* __restrict__ gu,
                                     uint16_t* __restrict__ hi,
                                     uint16_t* __restrict__ lo, int n) {
    int idx = blockIdx.x * blockDim.x + threadIdx.x;
    if (idx >= n) return;
    int m = idx >> 12;          // / FF_
    int j = idx & (FF_ - 1);
    float gv = gu[(size_t)m * GUW_ + j];
    float uv = gu[(size_t)m * GUW_ + FF_ + j];
    float sig = 1.f / (1.f + __expf(-gv));
    split_w(hi, lo, idx, gv * sig * uv);
}

// ---------------- driver ----------------------------------------------------
extern "C" void kernel_launch(void* const* d_in, const int* in_sizes, int n_in,
                              void* d_out, int out_size) {
    const int*   tokens     = (const int*)d_in[0];
    const float* embed      = (const float*)d_in[1];
    const float* wq         = (const float*)d_in[2];
    const float* wk         = (const float*)d_in[3];
    const float* wv         = (const float*)d_in[4];
    const float* wo         = (const float*)d_in[5];
    const float* w_gate     = (const float*)d_in[6];
    const float* w_up       = (const float*)d_in[7];
    const float* w_down     = (const float*)d_in[8];
    const float* norm1_w    = (const float*)d_in[9];
    const float* norm2_w    = (const float*)d_in[10];
    const float* final_norm = (const float*)d_in[11];
    float* out = (float*)d_out;

    float *x, *qkv, *gu;
    uint16_t *h_hi, *h_lo, *att_hi, *att_lo, *gs_hi, *gs_lo;
    uint16_t *wqkvt_hi, *wqkvt_lo, *wot_hi, *wot_lo, *wgut_hi, *wgut_lo, *wdt_hi, *wdt_lo;
    uint16_t *emb_hi, *emb_lo;
    cudaGetSymbolAddress((void**)&x,    g_x);
    cudaGetSymbolAddress((void**)&qkv,  g_qkv);
    cudaGetSymbolAddress((void**)&gu,   g_gu);
    cudaGetSymbolAddress((void**)&h_hi,   g_h_hi);
    cudaGetSymbolAddress((void**)&h_lo,   g_h_lo);
    cudaGetSymbolAddress((void**)&att_hi, g_att_hi);
    cudaGetSymbolAddress((void**)&att_lo, g_att_lo);
    cudaGetSymbolAddress((void**)&gs_hi,  g_gs_hi);
    cudaGetSymbolAddress((void**)&gs_lo,  g_gs_lo);
    cudaGetSymbolAddress((void**)&wqkvt_hi, g_wqkvt_hi);
    cudaGetSymbolAddress((void**)&wqkvt_lo, g_wqkvt_lo);
    cudaGetSymbolAddress((void**)&wot_hi,   g_wot_hi);
    cudaGetSymbolAddress((void**)&wot_lo,   g_wot_lo);
    cudaGetSymbolAddress((void**)&wgut_hi,  g_wgut_hi);
    cudaGetSymbolAddress((void**)&wgut_lo,  g_wgut_lo);
    cudaGetSymbolAddress((void**)&wdt_hi,   g_wdt_hi);
    cudaGetSymbolAddress((void**)&wdt_lo,   g_wdt_lo);
    cudaGetSymbolAddress((void**)&emb_hi,   g_emb_hi);
    cudaGetSymbolAddress((void**)&emb_lo,   g_emb_lo);

    cudaFuncSetAttribute(bf16x3_gemm<false>,
                         cudaFuncAttributeMaxDynamicSharedMemorySize, GEMM_SMEM_BYTES);
    cudaFuncSetAttribute(bf16x3_gemm<true>,
                         cudaFuncAttributeMaxDynamicSharedMemorySize, GEMM_SMEM_BYTES);

    embed_kernel<<<M_, 256>>>(tokens, embed, x);
    split4_kernel<<<(V_ * D_ / 4 + 255) / 256, 256>>>((const float4*)embed,
                                                      (uint2*)emb_hi, (uint2*)emb_lo,
                                                      V_ * D_ / 4);

    // ---- batched transposes for all layers (7 launches total) ----
    dim3 t32(32, 8);
    const size_t QKV_L = (size_t)QKVW_ * D_;
    const size_t GU_L  = (size_t)GUW_ * D_;
    transpose_split_batched<<<dim3(D_ / 32, QW_ / 32, L_), t32>>>(
        wq, wqkvt_hi, wqkvt_lo, D_, QW_, (size_t)D_ * QW_, QKV_L);
    transpose_split_batched<<<dim3(D_ / 32, KVW_ / 32, L_), t32>>>(
        wk, wqkvt_hi + (size_t)QW_ * D_, wqkvt_lo + (size_t)QW_ * D_,
        D_, KVW_, (size_t)D_ * KVW_, QKV_L);
    transpose_split_batched<<<dim3(D_ / 32, KVW_ / 32, L_), t32>>>(
        wv, wqkvt_hi + (size_t)(QW_ + KVW_) * D_, wqkvt_lo + (size_t)(QW_ + KVW_) * D_,
        D_, KVW_, (size_t)D_ * KVW_, QKV_L);
    transpose_split_batched<<<dim3(QW_ / 32, D_ / 32, L_), t32>>>(
        wo, wot_hi, wot_lo, QW_, D_, (size_t)QW_ * D_, (size_t)D_ * QW_);
    transpose_split_batched<<<dim3(D_ / 32, FF_ / 32, L_), t32>>>(
        w_gate, wgut_hi, wgut_lo, D_, FF_, (size_t)D_ * FF_, GU_L);
    transpose_split_batched<<<dim3(D_ / 32, FF_ / 32, L_), t32>>>(
        w_up, wgut_hi + (size_t)FF_ * D_, wgut_lo + (size_t)FF_ * D_,
        D_, FF_, (size_t)D_ * FF_, GU_L);
    transpose_split_batched<<<dim3(FF_ / 32, D_ / 32, L_), t32>>>(
        w_down, wdt_hi, wdt_lo, FF_, D_, (size_t)FF_ * D_, (size_t)D_ * FF_);

    for (int i = 0; i < L_; i++) {
        const uint16_t* wqkvt_hi_i = wqkvt_hi + (size_t)i * QKV_L;
        const uint16_t* wqkvt_lo_i = wqkvt_lo + (size_t)i * QKV_L;
        const uint16_t* wot_hi_i   = wot_hi + (size_t)i * D_ * QW_;
        const uint16_t* wot_lo_i   = wot_lo + (size_t)i * D_ * QW_;
        const uint16_t* wgut_hi_i  = wgut_hi + (size_t)i * GU_L;
        const uint16_t* wgut_lo_i  = wgut_lo + (size_t)i * GU_L;
        const uint16_t* wdt_hi_i   = wdt_hi + (size_t)i * D_ * FF_;
        const uint16_t* wdt_lo_i   = wdt_lo + (size_t)i * D_ * FF_;

        rmsnorm_split_kernel<<<M_, 256>>>(x, norm1_w + (size_t)i * D_, h_hi, h_lo);

        bf16x3_gemm<false><<<dim3(QKVW_ / 128, M_ / 128), 256, GEMM_SMEM_BYTES>>>(
            h_hi, h_lo, wqkvt_hi_i, wqkvt_lo_i, qkv, M_, QKVW_, D_);

        rope_kernel<<<(M_ * H_ * 32 + 255) / 256, 256>>>(qkv, H_, QKVW_, M_ * H_ * 32);
        rope_kernel<<<(M_ * HKV_ * 32 + 255) / 256, 256>>>(qkv + QW_, HKV_, QKVW_, M_ * HKV_ * 32);

        attn_kernel<<<dim3(B_ * HKV_, S_ / 2), 256>>>(qkv, att_hi, att_lo);

        bf16x3_gemm<true><<<dim3(D_ / 128, M_ / 128), 256, GEMM_SMEM_BYTES>>>(
            att_hi, att_lo, wot_hi_i, wot_lo_i, x, M_, D_, QW_);

        rmsnorm_split_kernel<<<M_, 256>>>(x, norm2_w + (size_t)i * D_, h_hi, h_lo);

        bf16x3_gemm<false><<<dim3(GUW_ / 128, M_ / 128), 256, GEMM_SMEM_BYTES>>>(
            h_hi, h_lo, wgut_hi_i, wgut_lo_i, gu, M_, GUW_, D_);

        silumul_split_kernel<<<(M_ * FF_ + 255) / 256, 256>>>(gu, gs_hi, gs_lo, M_ * FF_);

        bf16x3_gemm<true><<<dim3(D_ / 128, M_ / 128), 256, GEMM_SMEM_BYTES>>>(
            gs_hi, gs_lo, wdt_hi_i, wdt_lo_i, x, M_, D_, FF_);
    }

    rmsnorm_split_kernel<<<M_, 256>>>(x, final_norm, h_hi, h_lo);

    // logits = h @ embed^T ; embed is [V, D] = [N, K] row-major already
    bf16x3_gemm<false><<<dim3(V_ / 128, M_ / 128), 256, GEMM_SMEM_BYTES>>>(
        h_hi, h_lo, emb_hi, emb_lo, out, M_, V_, D_);
}